// round 8
// baseline (speedup 1.0000x reference)
#include <cuda_runtime.h>
#include <cuda_bf16.h>
#include <stdint.h>

// ---------------------------------------------------------------------------
// BiLSTM fp32. Round 8: rec kernel keeps mma.sync bf16x3 math but replaces the
// per-step lockstep global barrier with a pipelined per-producer flag protocol
// (acquire/release, double-buffered h image, drift <= 1 step), and moves the
// gate nonlinearities fully into registers via an R column permutation that
// gives each thread all 4 gates of its (row, unit) cells.
// GEMM / merge unchanged.
// ---------------------------------------------------------------------------

// ---- scratch (device globals; allocation is forbidden) --------------------
__device__ float g_xz[2][33554432];     // [dir][(b*T+t)*1024 + col]
__device__ float g_out1[2][8388608];    // [dir][(b*T+t)*256 + u]
__device__ float g_out2[2][8388608];
// h exchange image: [16 rows][264 k] bf16 hi plane (8448B) + lo plane (8448B)
__device__ __align__(16) unsigned char g_himg[2][2][8][16896];
__device__ unsigned g_prod[2][8][8];    // producer step flags (monotonic)
__device__ unsigned g_cons[2][8][8];    // consumer step flags (monotonic)
__device__ unsigned g_cnt[16];
__device__ volatile unsigned g_sns[16];

__device__ __forceinline__ float sigf(float x) {
    return 1.0f / (1.0f + __expf(-x));
}
__device__ __forceinline__ float tanhf_fast(float x) {
    return 2.0f / (1.0f + __expf(-2.0f * x)) - 1.0f;
}
__device__ __forceinline__ uint32_t smem_u32(const void* p) {
    uint32_t a;
    asm("{ .reg .u64 t; cvta.to.shared.u64 t, %1; cvt.u32.u64 %0, t; }"
        : "=r"(a) : "l"(p));
    return a;
}
__device__ __forceinline__ unsigned ld_acq(const unsigned* p) {
    unsigned v;
    asm volatile("ld.acquire.gpu.global.u32 %0, [%1];" : "=r"(v) : "l"(p) : "memory");
    return v;
}
__device__ __forceinline__ void st_rel(unsigned* p, unsigned v) {
    asm volatile("st.release.gpu.global.u32 [%0], %1;" :: "l"(p), "r"(v) : "memory");
}

#define LDSM4(r0, r1, r2, r3, addr) \
    asm volatile("ldmatrix.sync.aligned.m8n8.x4.shared.b16 {%0,%1,%2,%3}, [%4];" \
                 : "=r"(r0), "=r"(r1), "=r"(r2), "=r"(r3) : "r"(addr))

#define MMA16816(c0, c1, c2, c3, a0, a1, a2, a3, b0, b1) \
    asm volatile("mma.sync.aligned.m16n8k16.row.col.f32.bf16.bf16.f32 " \
                 "{%0,%1,%2,%3}, {%4,%5,%6,%7}, {%8,%9}, {%0,%1,%2,%3};" \
                 : "+f"(c0), "+f"(c1), "+f"(c2), "+f"(c3) \
                 : "r"(a0), "r"(a1), "r"(a2), "r"(a3), "r"(b0), "r"(b1))

// ---------------------------------------------------------------------------
// GEMM: C[M=32768, N=1024] = A[M,256] @ W[256,1024] + bias  (unchanged)
// ---------------------------------------------------------------------------
__global__ __launch_bounds__(256, 2) void gemm_xz_kernel(
    const float* __restrict__ x,
    const float* __restrict__ kfw, const float* __restrict__ kbw,
    const float* __restrict__ bfw, const float* __restrict__ bbw,
    int layer)
{
    const int dir = blockIdx.z;
    const float* __restrict__ A = (layer == 0) ? x : g_out1[dir];
    const float* __restrict__ W = (dir ? kbw : kfw) + layer * 262144;
    const float* __restrict__ bias = (dir ? bbw : bfw) + layer * 1024;
    float* __restrict__ C = g_xz[dir];

    const int m0 = blockIdx.y * 128;
    const int n0 = blockIdx.x * 128;

    __shared__ float As[8][132];
    __shared__ float Bs[8][132];

    const int tid = threadIdx.x;
    const int tx = tid & 15;
    const int ty = tid >> 4;
    const int ar = tid >> 1;
    const int ac = (tid & 1) << 2;
    const int br = tid >> 5;
    const int bc = (tid & 31) << 2;

    float acc[8][8];
#pragma unroll
    for (int i = 0; i < 8; i++)
#pragma unroll
        for (int j = 0; j < 8; j++) acc[i][j] = 0.0f;

    for (int k0 = 0; k0 < 256; k0 += 8) {
        float4 a0 = *(const float4*)&A[(m0 + ar) * 256 + k0 + ac];
        float4 b0 = *(const float4*)&W[(k0 + br) * 1024 + n0 + bc];
        __syncthreads();
        As[ac + 0][ar] = a0.x; As[ac + 1][ar] = a0.y;
        As[ac + 2][ar] = a0.z; As[ac + 3][ar] = a0.w;
        *(float4*)&Bs[br][bc] = b0;
        __syncthreads();
#pragma unroll
        for (int kk = 0; kk < 8; kk++) {
            float4 aa0 = *(const float4*)&As[kk][ty * 8];
            float4 aa1 = *(const float4*)&As[kk][ty * 8 + 4];
            float4 bb0 = *(const float4*)&Bs[kk][tx * 8];
            float4 bb1 = *(const float4*)&Bs[kk][tx * 8 + 4];
            float a[8] = {aa0.x, aa0.y, aa0.z, aa0.w, aa1.x, aa1.y, aa1.z, aa1.w};
            float b[8] = {bb0.x, bb0.y, bb0.z, bb0.w, bb1.x, bb1.y, bb1.z, bb1.w};
#pragma unroll
            for (int i = 0; i < 8; i++)
#pragma unroll
                for (int j = 0; j < 8; j++) acc[i][j] += a[i] * b[j];
        }
    }

    float4 bv0 = *(const float4*)&bias[n0 + tx * 8];
    float4 bv1 = *(const float4*)&bias[n0 + tx * 8 + 4];
    float bb[8] = {bv0.x, bv0.y, bv0.z, bv0.w, bv1.x, bv1.y, bv1.z, bv1.w};
#pragma unroll
    for (int i = 0; i < 8; i++) {
        float4 o0, o1;
        o0.x = acc[i][0] + bb[0]; o0.y = acc[i][1] + bb[1];
        o0.z = acc[i][2] + bb[2]; o0.w = acc[i][3] + bb[3];
        o1.x = acc[i][4] + bb[4]; o1.y = acc[i][5] + bb[5];
        o1.z = acc[i][6] + bb[6]; o1.w = acc[i][7] + bb[7];
        *(float4*)&C[(m0 + ty * 8 + i) * 1024 + n0 + tx * 8] = o0;
        *(float4*)&C[(m0 + ty * 8 + i) * 1024 + n0 + tx * 8 + 4] = o1;
    }
}

// ---------------------------------------------------------------------------
// Tensor-core recurrence, pipelined flag exchange.
// 128 CTAs = 2 dirs x 8 batch-tiles(16 rows) x 8 unit-tiles(32 units).
// Warp w tile: M=16, N=16 = units (u0+4w..u0+4w+3) x 4 gates (permuted cols:
// col j -> gate 2*(j>>3)+(j&1), unit (j>>1)&3). Thread (lane) C-fragments hold
// all 4 gates for (row=lane>>2 & +8, unit u0+4w+(lane&3)) -> gates in regs.
// ---------------------------------------------------------------------------
#define RP 264
#define OFF_RHI 0                   // 128*528 = 67584
#define OFF_RLO 67584
#define OFF_HHI 135168              // 16*528 hi + 16*528 lo
#define REC_SMEM_TOTAL (135168 + 16896)

__device__ __forceinline__ void group_barrier(int grp, unsigned* s_sense) {
    __syncthreads();
    if (threadIdx.x == 0) {
        unsigned ls = *s_sense ^ 1u;
        *s_sense = ls;
        __threadfence();
        unsigned v = atomicAdd(&g_cnt[grp], 1u);
        if (v == 7u) {
            g_cnt[grp] = 0u;
            __threadfence();
            g_sns[grp] = ls;
        } else {
            while (g_sns[grp] != ls) { }
        }
    }
    __syncthreads();
}

__global__ __launch_bounds__(256, 1) void rec_mma_kernel(
    const float* __restrict__ rfw, const float* __restrict__ rbw, int layer)
{
    extern __shared__ unsigned char smx[];

    const int bx  = blockIdx.x;
    const int dir = bx >> 6;
    const int ut  = bx & 7;
    const int grp = bx >> 3;
    const int bt  = (bx >> 3) & 7;
    const int b0  = bt * 16;
    const int u0  = ut * 32;

    const float* __restrict__ R  = (dir ? rbw : rfw) + layer * 262144;
    const float* __restrict__ xz = g_xz[dir];
    float* __restrict__ outp     = layer ? g_out2[dir] : g_out1[dir];

    const int tid  = threadIdx.x;
    const int lane = tid & 31;
    const int w    = tid >> 5;

    unsigned* prodf = g_prod[dir][bt];
    unsigned* consf = g_cons[dir][bt];

    __shared__ unsigned s_sense;
    if (tid == 0) s_sense = g_sns[grp];

    // ---- load R slice -> R^T bf16 hi/lo planes, gate-interleaved cols ----
    // tile col ci: w=ci>>4, j=ci&15 -> gate g=2*(j>>3)+(j&1), unit v=(j>>1)&3
    // orig col = g*256 + u0 + 4*(ci>>4) + v
    for (int i = tid; i < 128 * 256; i += 256) {
        int ci = i & 127;
        int k  = i >> 7;
        int j  = ci & 15;
        int g  = 2 * (j >> 3) + (j & 1);
        int v  = (j >> 1) & 3;
        float rv = R[k * 1024 + g * 256 + u0 + 4 * (ci >> 4) + v];
        __nv_bfloat16 hi = __float2bfloat16(rv);
        __nv_bfloat16 lo = __float2bfloat16(rv - __bfloat162float(hi));
        *(__nv_bfloat16*)(smx + OFF_RHI + (ci * RP + k) * 2) = hi;
        *(__nv_bfloat16*)(smx + OFF_RLO + (ci * RP + k) * 2) = lo;
    }

    // ---- zero own slice of phase-0 image, publish prod=1 ("image 0 ready")
    {
        unsigned char* img = g_himg[dir][0][bt];
        for (int i = tid; i < 128; i += 256) {
            int q = i >> 6, r = (i >> 2) & 15, part = i & 3;
            *(uint4*)(img + q * 8448 + r * 528 + u0 * 2 + part * 16) =
                make_uint4(0, 0, 0, 0);
        }
    }
    __syncthreads();
    if (tid == 0) {
        __threadfence();
        st_rel(&prodf[ut], 1u);
    }

    // ---- per-thread ldmatrix byte offsets ----
    const int arow = (lane & 7) + 8 * ((lane >> 3) & 1);
    const int aoff = arow * (RP * 2) + 8 * (lane >> 4) * 2;
    const int n0w  = w * 16;
    const int brow = n0w + (lane & 7) + 8 * ((lane >> 4) & 1);
    const int boff = brow * (RP * 2) + 8 * ((lane >> 3) & 1) * 2;
    const uint32_t aHi = smem_u32(smx + OFF_HHI) + aoff;
    const uint32_t aLo = aHi + 8448;
    const uint32_t bHi = smem_u32(smx + OFF_RHI) + boff;
    const uint32_t bLo = smem_u32(smx + OFF_RLO) + boff;

    // thread cell coordinates
    const int m_r = lane >> 2;                 // rows m_r, m_r+8
    const int U   = u0 + 4 * w + (lane & 3);   // unit
    float cst[2] = {0.0f, 0.0f};

    // consumer copy coordinates (warp w copies producer slice w)
    const int cq = lane >> 4;                  // plane
    const int cr = lane & 15;                  // row
    const unsigned char* gimg[2] = { g_himg[dir][0][bt], g_himg[dir][1][bt] };

    for (int s = 0; s < 256; s++) {
        const int t = dir ? (255 - s) : s;

        // ---- C fragments init from xz (gates i,f,g,o at cols g*256+U) ----
        float c0[4], c1[4];
        {
            const float* xb  = xz + ((size_t)(b0 + m_r) * 256 + t) * 1024 + U;
            const float* xb8 = xb + (size_t)8 * 256 * 1024;
            c0[0] = __ldg(xb);         c0[1] = __ldg(xb + 256);
            c1[0] = __ldg(xb + 512);   c1[1] = __ldg(xb + 768);
            c0[2] = __ldg(xb8);        c0[3] = __ldg(xb8 + 256);
            c1[2] = __ldg(xb8 + 512);  c1[3] = __ldg(xb8 + 768);
        }

        // ---- copy h image: warp w waits for producer w, copies slice w ----
        {
            if (lane == 0) {
                while (ld_acq(&prodf[w]) < (unsigned)(s + 1)) { }
            }
            __syncwarp();
            const unsigned char* src = gimg[s & 1] + cq * 8448 + cr * 528 + w * 64;
            unsigned char* dst = smx + OFF_HHI + cq * 8448 + cr * 528 + w * 64;
#pragma unroll
            for (int j = 0; j < 4; j++) {
                uint4 v = __ldcg((const uint4*)(src + j * 16));
                *(uint4*)(dst + j * 16) = v;
            }
        }
        __syncthreads();
        if (tid == 0) st_rel(&consf[ut], (unsigned)(s + 1));

        // ---- 16 k-steps x (4 ldmatrix.x4 + 6 mma), bf16x3 split ----
#pragma unroll 4
        for (int ks = 0; ks < 16; ks++) {
            uint32_t ah0, ah1, ah2, ah3, al0, al1, al2, al3;
            uint32_t bh0, bh1, bh2, bh3, bl0, bl1, bl2, bl3;
            LDSM4(ah0, ah1, ah2, ah3, aHi + 32 * ks);
            LDSM4(bh0, bh1, bh2, bh3, bHi + 32 * ks);
            LDSM4(al0, al1, al2, al3, aLo + 32 * ks);
            LDSM4(bl0, bl1, bl2, bl3, bLo + 32 * ks);
            MMA16816(c0[0], c0[1], c0[2], c0[3], ah0, ah1, ah2, ah3, bh0, bh1);
            MMA16816(c1[0], c1[1], c1[2], c1[3], ah0, ah1, ah2, ah3, bh2, bh3);
            MMA16816(c0[0], c0[1], c0[2], c0[3], al0, al1, al2, al3, bh0, bh1);
            MMA16816(c1[0], c1[1], c1[2], c1[3], al0, al1, al2, al3, bh2, bh3);
            MMA16816(c0[0], c0[1], c0[2], c0[3], ah0, ah1, ah2, ah3, bl0, bl1);
            MMA16816(c1[0], c1[1], c1[2], c1[3], ah0, ah1, ah2, ah3, bl2, bl3);
        }

        // ---- gates fully in registers: cell0=(m_r,U), cell1=(m_r+8,U) ----
        float hv0, hv1;
        {
            float ig = sigf(c0[0]);
            float fg = sigf(c0[1]);
            float gg = tanhf_fast(c1[0]);
            float og = sigf(c1[1]);
            float cc = fg * cst[0] + ig * gg;
            cst[0] = cc;
            hv0 = og * tanhf_fast(cc);
            ig = sigf(c0[2]);
            fg = sigf(c0[3]);
            gg = tanhf_fast(c1[2]);
            og = sigf(c1[3]);
            cc = fg * cst[1] + ig * gg;
            cst[1] = cc;
            hv1 = og * tanhf_fast(cc);
        }

        // ---- ensure all consumers finished with the buffer we overwrite ----
        if (tid == 0) {
#pragma unroll
            for (int p = 0; p < 8; p++)
                while (ld_acq(&consf[p]) < (unsigned)s) { }
        }
        __syncthreads();

        // ---- write outputs + h image slice for step s+1 ----
        {
            outp[((size_t)(b0 + m_r) * 256 + t) * 256 + U]     = hv0;
            outp[((size_t)(b0 + m_r + 8) * 256 + t) * 256 + U] = hv1;

            unsigned char* img = (unsigned char*)gimg[(s + 1) & 1];
            __nv_bfloat16 h0 = __float2bfloat16(hv0);
            __nv_bfloat16 h1 = __float2bfloat16(hv1);
            __nv_bfloat16 l0 = __float2bfloat16(hv0 - __bfloat162float(h0));
            __nv_bfloat16 l1 = __float2bfloat16(hv1 - __bfloat162float(h1));
            *(__nv_bfloat16*)(img + m_r * 528 + U * 2)             = h0;
            *(__nv_bfloat16*)(img + (m_r + 8) * 528 + U * 2)       = h1;
            *(__nv_bfloat16*)(img + 8448 + m_r * 528 + U * 2)      = l0;
            *(__nv_bfloat16*)(img + 8448 + (m_r + 8) * 528 + U * 2) = l1;
        }
        __syncthreads();
        if (tid == 0) {
            __threadfence();
            st_rel(&prodf[ut], (unsigned)(s + 2));
        }
    }

    // ---- end barrier + flag reset (for graph replays / next launch) ----
    group_barrier(grp, &s_sense);
    if (tid == 0) {
        prodf[ut] = 0u;
        consf[ut] = 0u;
    }
}

// ---------------------------------------------------------------------------
// Merge: out = 0.5 * (out2f + out1f + out2b + out1b)  (residual + average)
// ---------------------------------------------------------------------------
__global__ __launch_bounds__(256) void merge_kernel(float4* __restrict__ out) {
    int i = blockIdx.x * blockDim.x + threadIdx.x;
    const float4* a = (const float4*)g_out1[0];
    const float4* b = (const float4*)g_out2[0];
    const float4* c = (const float4*)g_out1[1];
    const float4* d = (const float4*)g_out2[1];
    float4 va = a[i], vb = b[i], vc = c[i], vd = d[i];
    float4 o;
    o.x = 0.5f * (va.x + vb.x + vc.x + vd.x);
    o.y = 0.5f * (va.y + vb.y + vc.y + vd.y);
    o.z = 0.5f * (va.z + vb.z + vc.z + vd.z);
    o.w = 0.5f * (va.w + vb.w + vc.w + vd.w);
    out[i] = o;
}

// ---------------------------------------------------------------------------
extern "C" void kernel_launch(void* const* d_in, const int* in_sizes, int n_in,
                              void* d_out, int out_size) {
    (void)in_sizes; (void)n_in; (void)out_size;
    const float* x   = (const float*)d_in[0];
    const float* kfw = (const float*)d_in[1];
    const float* rfw = (const float*)d_in[2];
    const float* bfw = (const float*)d_in[3];
    const float* kbw = (const float*)d_in[4];
    const float* rbw = (const float*)d_in[5];
    const float* bbw = (const float*)d_in[6];
    float* out = (float*)d_out;

    cudaFuncSetAttribute(rec_mma_kernel,
                         cudaFuncAttributeMaxDynamicSharedMemorySize,
                         REC_SMEM_TOTAL);

    dim3 gg(8, 256, 2);
    gemm_xz_kernel<<<gg, 256>>>(x, kfw, kbw, bfw, bbw, 0);
    rec_mma_kernel<<<128, 256, REC_SMEM_TOTAL>>>(rfw, rbw, 0);
    gemm_xz_kernel<<<gg, 256>>>(x, kfw, kbw, bfw, bbw, 1);
    rec_mma_kernel<<<128, 256, REC_SMEM_TOTAL>>>(rfw, rbw, 1);
    merge_kernel<<<8192, 256>>>((float4*)out);
}

// round 10
// speedup vs baseline: 1.6889x; 1.6889x over previous
#include <cuda_runtime.h>
#include <cuda_bf16.h>
#include <stdint.h>

// ---------------------------------------------------------------------------
// BiLSTM fp32. Round 10 (= round 9 with compile fix):
//  - rec: round-7 version minus the all-thread per-step __threadfence
//    (barrier-internal tid0 fence retained; pattern proven in rounds 1-5).
//  - gemm: mma.sync bf16x3 (same validated frag mappings as rec).
//  - fix: bf2pack built from two __float2bfloat16 (API misuse corrected).
// ---------------------------------------------------------------------------

// ---- scratch (device globals; allocation is forbidden) --------------------
__device__ float g_xz[2][33554432];     // [dir][(b*T+t)*1024 + col]
__device__ float g_out1[2][8388608];    // [dir][(b*T+t)*256 + u]
__device__ float g_out2[2][8388608];
__device__ __align__(16) unsigned char g_himg[2][2][8][16896];
__device__ unsigned g_cnt[16];
__device__ volatile unsigned g_sns[16];

__device__ __forceinline__ float sigf(float x) {
    return 1.0f / (1.0f + __expf(-x));
}
__device__ __forceinline__ float tanhf_fast(float x) {
    return 2.0f / (1.0f + __expf(-2.0f * x)) - 1.0f;
}
__device__ __forceinline__ uint32_t smem_u32(const void* p) {
    uint32_t a;
    asm("{ .reg .u64 t; cvta.to.shared.u64 t, %1; cvt.u32.u64 %0, t; }"
        : "=r"(a) : "l"(p));
    return a;
}
__device__ __forceinline__ uint32_t bf2pack(float a, float b) {
    __nv_bfloat16 lo = __float2bfloat16(a);
    __nv_bfloat16 hi = __float2bfloat16(b);
    return (uint32_t)__bfloat16_as_ushort(lo)
         | ((uint32_t)__bfloat16_as_ushort(hi) << 16);
}

#define LDSM4(r0, r1, r2, r3, addr) \
    asm volatile("ldmatrix.sync.aligned.m8n8.x4.shared.b16 {%0,%1,%2,%3}, [%4];" \
                 : "=r"(r0), "=r"(r1), "=r"(r2), "=r"(r3) : "r"(addr))

#define MMA16816(c0, c1, c2, c3, a0, a1, a2, a3, b0, b1) \
    asm volatile("mma.sync.aligned.m16n8k16.row.col.f32.bf16.bf16.f32 " \
                 "{%0,%1,%2,%3}, {%4,%5,%6,%7}, {%8,%9}, {%0,%1,%2,%3};" \
                 : "+f"(c0), "+f"(c1), "+f"(c2), "+f"(c3) \
                 : "r"(a0), "r"(a1), "r"(a2), "r"(a3), "r"(b0), "r"(b1))

// ---------------------------------------------------------------------------
// Tensor-core GEMM: C[32768,1024] = A[32768,256] @ W[256,1024] + bias
// Tile 128x128, 8 warps x (32m x 64n), K-chunks of 64 with in-flight fp32->
// bf16 hi/lo conversion, bf16x3 split (hi*hi + lo*hi + hi*lo), fp32 accum.
// grid = (8, 256, 2); z = direction.
// ---------------------------------------------------------------------------
#define GROW 144                      // padded k row pitch in bytes (72 bf16)
#define GOFF_AHI 0                    // 128*144 = 18432
#define GOFF_ALO 18432
#define GOFF_BHI 36864
#define GOFF_BLO 55296
#define GEMM_SMEM 73728

__global__ __launch_bounds__(256, 2) void gemm_tc_kernel(
    const float* __restrict__ x,
    const float* __restrict__ kfw, const float* __restrict__ kbw,
    const float* __restrict__ bfw, const float* __restrict__ bbw,
    int layer)
{
    extern __shared__ unsigned char gsm[];
    const int dir = blockIdx.z;
    const float* __restrict__ A = (layer == 0) ? x : g_out1[dir];
    const float* __restrict__ W = (dir ? kbw : kfw) + layer * 262144;
    const float* __restrict__ bias = (dir ? bbw : bfw) + layer * 1024;
    float* __restrict__ C = g_xz[dir];

    const int m0 = blockIdx.y * 128;
    const int n0 = blockIdx.x * 128;

    const int tid  = threadIdx.x;
    const int lane = tid & 31;
    const int w    = tid >> 5;
    const int wm   = w >> 1;          // m-tile 0..3 (32 rows each)
    const int wn   = w & 1;           // n-tile 0..1 (64 cols each)

    // ldmatrix offsets (validated pattern from rec kernel)
    const int aoff = ((lane & 7) + 8 * ((lane >> 3) & 1)) * GROW + 16 * (lane >> 4);
    const int boff = ((lane & 7) + 8 * ((lane >> 4) & 1)) * GROW
                   + 16 * ((lane >> 3) & 1);
    const uint32_t aHiB = smem_u32(gsm + GOFF_AHI) + wm * 32 * GROW + aoff;
    const uint32_t aLoB = smem_u32(gsm + GOFF_ALO) + wm * 32 * GROW + aoff;
    const uint32_t bHiB = smem_u32(gsm + GOFF_BHI) + wn * 64 * GROW + boff;
    const uint32_t bLoB = smem_u32(gsm + GOFF_BLO) + wn * 64 * GROW + boff;

    // accumulators [mi*8 + ni][4], initialized with bias (exact fp32 add)
    float c[16][4];
#pragma unroll
    for (int ng = 0; ng < 4; ng++)
#pragma unroll
        for (int h = 0; h < 2; h++) {
            float2 bv = *(const float2*)&bias[n0 + wn * 64 + ng * 16 + h * 8
                                              + 2 * (lane & 3)];
#pragma unroll
            for (int mi = 0; mi < 2; mi++) {
                int f = mi * 8 + 2 * ng + h;
                c[f][0] = bv.x; c[f][1] = bv.y;
                c[f][2] = bv.x; c[f][3] = bv.y;
            }
        }

    for (int kc = 0; kc < 256; kc += 64) {
        // --- load + convert A chunk [128 m][64 k] ---
#pragma unroll
        for (int j = 0; j < 8; j++) {
            int idx = tid + 256 * j;          // 2048 float4s
            int r = idx >> 4, c4 = idx & 15;
            float4 v = *(const float4*)&A[(size_t)(m0 + r) * 256 + kc + c4 * 4];
            __nv_bfloat16 hx = __float2bfloat16(v.x);
            __nv_bfloat16 hy = __float2bfloat16(v.y);
            __nv_bfloat16 hz = __float2bfloat16(v.z);
            __nv_bfloat16 hw = __float2bfloat16(v.w);
            uint2 hi, lo;
            hi.x = ((uint32_t)__bfloat16_as_ushort(hx))
                 | ((uint32_t)__bfloat16_as_ushort(hy) << 16);
            hi.y = ((uint32_t)__bfloat16_as_ushort(hz))
                 | ((uint32_t)__bfloat16_as_ushort(hw) << 16);
            lo.x = bf2pack(v.x - __bfloat162float(hx), v.y - __bfloat162float(hy));
            lo.y = bf2pack(v.z - __bfloat162float(hz), v.w - __bfloat162float(hw));
            *(uint2*)(gsm + GOFF_AHI + r * GROW + c4 * 8) = hi;
            *(uint2*)(gsm + GOFF_ALO + r * GROW + c4 * 8) = lo;
        }
        // --- load + convert W chunk -> B planes [128 n][64 k] (transposed) ---
#pragma unroll
        for (int j = 0; j < 8; j++) {
            int idx = tid + 256 * j;
            int k = idx >> 5, n4 = idx & 31;
            float4 v = *(const float4*)&W[(size_t)(kc + k) * 1024 + n0 + n4 * 4];
            float e[4] = {v.x, v.y, v.z, v.w};
#pragma unroll
            for (int q = 0; q < 4; q++) {
                __nv_bfloat16 hb = __float2bfloat16(e[q]);
                __nv_bfloat16 lb = __float2bfloat16(e[q] - __bfloat162float(hb));
                *(__nv_bfloat16*)(gsm + GOFF_BHI + (n4 * 4 + q) * GROW + k * 2) = hb;
                *(__nv_bfloat16*)(gsm + GOFF_BLO + (n4 * 4 + q) * GROW + k * 2) = lb;
            }
        }
        __syncthreads();

#pragma unroll
        for (int ks = 0; ks < 4; ks++) {
            uint32_t ah[2][4], al[2][4];
#pragma unroll
            for (int mi = 0; mi < 2; mi++) {
                LDSM4(ah[mi][0], ah[mi][1], ah[mi][2], ah[mi][3],
                      aHiB + mi * 16 * GROW + 32 * ks);
                LDSM4(al[mi][0], al[mi][1], al[mi][2], al[mi][3],
                      aLoB + mi * 16 * GROW + 32 * ks);
            }
#pragma unroll
            for (int ng = 0; ng < 4; ng++) {
                uint32_t bh[4], bl[4];
                LDSM4(bh[0], bh[1], bh[2], bh[3], bHiB + ng * 16 * GROW + 32 * ks);
                LDSM4(bl[0], bl[1], bl[2], bl[3], bLoB + ng * 16 * GROW + 32 * ks);
#pragma unroll
                for (int mi = 0; mi < 2; mi++) {
                    int f0 = mi * 8 + 2 * ng, f1 = f0 + 1;
                    MMA16816(c[f0][0], c[f0][1], c[f0][2], c[f0][3],
                             ah[mi][0], ah[mi][1], ah[mi][2], ah[mi][3], bh[0], bh[1]);
                    MMA16816(c[f1][0], c[f1][1], c[f1][2], c[f1][3],
                             ah[mi][0], ah[mi][1], ah[mi][2], ah[mi][3], bh[2], bh[3]);
                    MMA16816(c[f0][0], c[f0][1], c[f0][2], c[f0][3],
                             al[mi][0], al[mi][1], al[mi][2], al[mi][3], bh[0], bh[1]);
                    MMA16816(c[f1][0], c[f1][1], c[f1][2], c[f1][3],
                             al[mi][0], al[mi][1], al[mi][2], al[mi][3], bh[2], bh[3]);
                    MMA16816(c[f0][0], c[f0][1], c[f0][2], c[f0][3],
                             ah[mi][0], ah[mi][1], ah[mi][2], ah[mi][3], bl[0], bl[1]);
                    MMA16816(c[f1][0], c[f1][1], c[f1][2], c[f1][3],
                             ah[mi][0], ah[mi][1], ah[mi][2], ah[mi][3], bl[2], bl[3]);
                }
            }
        }
        __syncthreads();
    }

    // epilogue: standard m16n8 fragment layout
    const int r0 = m0 + wm * 32 + (lane >> 2);
    const int cb = n0 + wn * 64 + 2 * (lane & 3);
#pragma unroll
    for (int mi = 0; mi < 2; mi++)
#pragma unroll
        for (int ni = 0; ni < 8; ni++) {
            int f = mi * 8 + ni;
            int col = cb + ni * 8;
            *(float2*)&C[(size_t)(r0 + mi * 16) * 1024 + col] =
                make_float2(c[f][0], c[f][1]);
            *(float2*)&C[(size_t)(r0 + mi * 16 + 8) * 1024 + col] =
                make_float2(c[f][2], c[f][3]);
        }
}

// ---------------------------------------------------------------------------
// Tensor-core recurrence (round-7 version; all-thread per-step fence removed).
// 128 CTAs = 2 dirs x 8 batch-tiles(16 rows) x 8 unit-tiles(32 units x 4 gates)
// ---------------------------------------------------------------------------
#define RP 264
#define OFF_RHI 0
#define OFF_RLO 67584
#define OFF_HHI 135168
#define OFF_HLO 143616
#define OFF_Z   152064
#define REC_SMEM_TOTAL (152064 + 8448)

__device__ __forceinline__ void group_barrier(int grp, unsigned* s_sense) {
    __syncthreads();
    if (threadIdx.x == 0) {
        unsigned ls = *s_sense ^ 1u;
        *s_sense = ls;
        __threadfence();
        unsigned v = atomicAdd(&g_cnt[grp], 1u);
        if (v == 7u) {
            g_cnt[grp] = 0u;
            __threadfence();
            g_sns[grp] = ls;
        } else {
            while (g_sns[grp] != ls) { }
        }
    }
    __syncthreads();
}

__global__ __launch_bounds__(256, 1) void rec_mma_kernel(
    const float* __restrict__ rfw, const float* __restrict__ rbw, int layer)
{
    extern __shared__ unsigned char smx[];
    float* zsm = (float*)(smx + OFF_Z);

    const int bx  = blockIdx.x;
    const int dir = bx >> 6;
    const int ut  = bx & 7;
    const int grp = bx >> 3;
    const int bt  = (bx >> 3) & 7;
    const int b0  = bt * 16;
    const int u0  = ut * 32;

    const float* __restrict__ R  = (dir ? rbw : rfw) + layer * 262144;
    const float* __restrict__ xz = g_xz[dir];
    float* __restrict__ outp     = layer ? g_out2[dir] : g_out1[dir];

    const int tid  = threadIdx.x;
    const int lane = tid & 31;
    const int w    = tid >> 5;

    __shared__ unsigned s_sense;
    if (tid == 0) s_sense = g_sns[grp];

    for (int i = tid; i < 128 * 256; i += 256) {
        int ci = i & 127;
        int k  = i >> 7;
        float rv = R[k * 1024 + (ci >> 5) * 256 + u0 + (ci & 31)];
        __nv_bfloat16 hi = __float2bfloat16(rv);
        __nv_bfloat16 lo = __float2bfloat16(rv - __bfloat162float(hi));
        *(__nv_bfloat16*)(smx + OFF_RHI + (ci * RP + k) * 2) = hi;
        *(__nv_bfloat16*)(smx + OFF_RLO + (ci * RP + k) * 2) = lo;
    }

    {
        uint4* dst = (uint4*)g_himg[dir][0][bt];
        for (int i = tid; i < 1056; i += 256) dst[i] = make_uint4(0, 0, 0, 0);
    }
    __threadfence();
    group_barrier(grp, &s_sense);

    const int arow  = (lane & 7) + 8 * ((lane >> 3) & 1);
    const int aoff  = arow * (RP * 2) + 8 * (lane >> 4) * 2;
    const int n0w   = w * 16;
    const int brow  = n0w + (lane & 7) + 8 * ((lane >> 4) & 1);
    const int boff  = brow * (RP * 2) + 8 * ((lane >> 3) & 1) * 2;
    const uint32_t aHi = smem_u32(smx + OFF_HHI) + aoff;
    const uint32_t aLo = smem_u32(smx + OFF_HLO) + aoff;
    const uint32_t bHi = smem_u32(smx + OFF_RHI) + boff;
    const uint32_t bLo = smem_u32(smx + OFF_RLO) + boff;

    const int m_r   = lane >> 2;
    const int ccol  = 2 * (lane & 3);
    const int gcol0 = (w >> 1) * 256 + u0 + 16 * (w & 1) + ccol;

    const int gr  = tid >> 4;
    const int gu2 = (tid & 15) * 2;
    float cst[2] = {0.0f, 0.0f};

    for (int s = 0; s < 256; s++) {
        const int t = dir ? (255 - s) : s;

        float c0[4], c1[4];
        {
            const float* xb = xz + ((size_t)(b0 + m_r) * 256 + t) * 1024 + gcol0;
            const float* xb8 = xb + (size_t)8 * 256 * 1024;
            float2 v00 = *(const float2*)xb;
            float2 v01 = *(const float2*)(xb + 8);
            float2 v10 = *(const float2*)xb8;
            float2 v11 = *(const float2*)(xb8 + 8);
            c0[0] = v00.x; c0[1] = v00.y; c0[2] = v10.x; c0[3] = v10.y;
            c1[0] = v01.x; c1[1] = v01.y; c1[2] = v11.x; c1[3] = v11.y;
        }

        {
            const uint4* src = (const uint4*)g_himg[dir][s & 1][bt];
            uint4* dst = (uint4*)(smx + OFF_HHI);
            for (int i = tid; i < 1056; i += 256) dst[i] = __ldcg(src + i);
        }
        __syncthreads();

#pragma unroll 4
        for (int ks = 0; ks < 16; ks++) {
            uint32_t ah0, ah1, ah2, ah3, al0, al1, al2, al3;
            uint32_t bh0, bh1, bh2, bh3, bl0, bl1, bl2, bl3;
            LDSM4(ah0, ah1, ah2, ah3, aHi + 32 * ks);
            LDSM4(bh0, bh1, bh2, bh3, bHi + 32 * ks);
            LDSM4(al0, al1, al2, al3, aLo + 32 * ks);
            LDSM4(bl0, bl1, bl2, bl3, bLo + 32 * ks);
            MMA16816(c0[0], c0[1], c0[2], c0[3], ah0, ah1, ah2, ah3, bh0, bh1);
            MMA16816(c1[0], c1[1], c1[2], c1[3], ah0, ah1, ah2, ah3, bh2, bh3);
            MMA16816(c0[0], c0[1], c0[2], c0[3], al0, al1, al2, al3, bh0, bh1);
            MMA16816(c1[0], c1[1], c1[2], c1[3], al0, al1, al2, al3, bh2, bh3);
            MMA16816(c0[0], c0[1], c0[2], c0[3], ah0, ah1, ah2, ah3, bl0, bl1);
            MMA16816(c1[0], c1[1], c1[2], c1[3], ah0, ah1, ah2, ah3, bl2, bl3);
        }

        {
            int cb = n0w + ccol;
            *(float2*)&zsm[m_r * 132 + cb]       = make_float2(c0[0], c0[1]);
            *(float2*)&zsm[(m_r + 8) * 132 + cb] = make_float2(c0[2], c0[3]);
            *(float2*)&zsm[m_r * 132 + cb + 8]       = make_float2(c1[0], c1[1]);
            *(float2*)&zsm[(m_r + 8) * 132 + cb + 8] = make_float2(c1[2], c1[3]);
        }
        __syncthreads();

        {
            unsigned char* img = g_himg[dir][(s + 1) & 1][bt];
            float hv[2];
#pragma unroll
            for (int j = 0; j < 2; j++) {
                int uu = gu2 + j;
                float zi = zsm[gr * 132 + uu];
                float zf = zsm[gr * 132 + 32 + uu];
                float zg = zsm[gr * 132 + 64 + uu];
                float zo = zsm[gr * 132 + 96 + uu];
                float ig = sigf(zi);
                float fg = sigf(zf);
                float gg = tanhf_fast(zg);
                float og = sigf(zo);
                float cc = fg * cst[j] + ig * gg;
                cst[j] = cc;
                hv[j] = og * tanhf_fast(cc);
            }
            *(float2*)&outp[((size_t)(b0 + gr) * 256 + t) * 256 + u0 + gu2] =
                make_float2(hv[0], hv[1]);
            __nv_bfloat16 h0 = __float2bfloat16(hv[0]);
            __nv_bfloat16 h1 = __float2bfloat16(hv[1]);
            __nv_bfloat16 l0 = __float2bfloat16(hv[0] - __bfloat162float(h0));
            __nv_bfloat16 l1 = __float2bfloat16(hv[1] - __bfloat162float(h1));
            uint32_t whi = (uint32_t)__bfloat16_as_ushort(h0)
                         | ((uint32_t)__bfloat16_as_ushort(h1) << 16);
            uint32_t wlo = (uint32_t)__bfloat16_as_ushort(l0)
                         | ((uint32_t)__bfloat16_as_ushort(l1) << 16);
            int cidx = u0 + gu2;
            *(uint32_t*)(img + (gr * RP + cidx) * 2)        = whi;
            *(uint32_t*)(img + 8448 + (gr * RP + cidx) * 2) = wlo;
        }

        group_barrier(grp, &s_sense);
    }
}

// ---------------------------------------------------------------------------
// Merge: out = 0.5 * (out2f + out1f + out2b + out1b)  (residual + average)
// ---------------------------------------------------------------------------
__global__ __launch_bounds__(256) void merge_kernel(float4* __restrict__ out) {
    int i = blockIdx.x * blockDim.x + threadIdx.x;
    const float4* a = (const float4*)g_out1[0];
    const float4* b = (const float4*)g_out2[0];
    const float4* c = (const float4*)g_out1[1];
    const float4* d = (const float4*)g_out2[1];
    float4 va = a[i], vb = b[i], vc = c[i], vd = d[i];
    float4 o;
    o.x = 0.5f * (va.x + vb.x + vc.x + vd.x);
    o.y = 0.5f * (va.y + vb.y + vc.y + vd.y);
    o.z = 0.5f * (va.z + vb.z + vc.z + vd.z);
    o.w = 0.5f * (va.w + vb.w + vc.w + vd.w);
    out[i] = o;
}

// ---------------------------------------------------------------------------
extern "C" void kernel_launch(void* const* d_in, const int* in_sizes, int n_in,
                              void* d_out, int out_size) {
    (void)in_sizes; (void)n_in; (void)out_size;
    const float* x   = (const float*)d_in[0];
    const float* kfw = (const float*)d_in[1];
    const float* rfw = (const float*)d_in[2];
    const float* bfw = (const float*)d_in[3];
    const float* kbw = (const float*)d_in[4];
    const float* rbw = (const float*)d_in[5];
    const float* bbw = (const float*)d_in[6];
    float* out = (float*)d_out;

    cudaFuncSetAttribute(rec_mma_kernel,
                         cudaFuncAttributeMaxDynamicSharedMemorySize,
                         REC_SMEM_TOTAL);
    cudaFuncSetAttribute(gemm_tc_kernel,
                         cudaFuncAttributeMaxDynamicSharedMemorySize,
                         GEMM_SMEM);

    dim3 gg(8, 256, 2);
    gemm_tc_kernel<<<gg, 256, GEMM_SMEM>>>(x, kfw, kbw, bfw, bbw, 0);
    rec_mma_kernel<<<128, 256, REC_SMEM_TOTAL>>>(rfw, rbw, 0);
    gemm_tc_kernel<<<gg, 256, GEMM_SMEM>>>(x, kfw, kbw, bfw, bbw, 1);
    rec_mma_kernel<<<128, 256, REC_SMEM_TOTAL>>>(rfw, rbw, 1);
    merge_kernel<<<8192, 256>>>((float4*)out);
}

// round 11
// speedup vs baseline: 1.7565x; 1.0401x over previous
#include <cuda_runtime.h>
#include <cuda_bf16.h>
#include <stdint.h>

// ---------------------------------------------------------------------------
// BiLSTM fp32. Round 11: rec kernel widened to 512 threads via split-K warp
// pairs (warp w: K-steps 0-7, warp w+8: K-steps 8-15, z partials reduced in
// SMEM during the gate phase). 4 warps/SMSP for latency hiding. Gate phase
// and all exchange machinery unchanged from the 4159us round-10 kernel.
// ---------------------------------------------------------------------------

// ---- scratch (device globals; allocation is forbidden) --------------------
__device__ float g_xz[2][33554432];     // [dir][(b*T+t)*1024 + col]
__device__ float g_out1[2][8388608];    // [dir][(b*T+t)*256 + u]
__device__ float g_out2[2][8388608];
__device__ __align__(16) unsigned char g_himg[2][2][8][16896];
__device__ unsigned g_cnt[16];
__device__ volatile unsigned g_sns[16];

__device__ __forceinline__ float sigf(float x) {
    return 1.0f / (1.0f + __expf(-x));
}
__device__ __forceinline__ float tanhf_fast(float x) {
    return 2.0f / (1.0f + __expf(-2.0f * x)) - 1.0f;
}
__device__ __forceinline__ uint32_t smem_u32(const void* p) {
    uint32_t a;
    asm("{ .reg .u64 t; cvta.to.shared.u64 t, %1; cvt.u32.u64 %0, t; }"
        : "=r"(a) : "l"(p));
    return a;
}
__device__ __forceinline__ uint32_t bf2pack(float a, float b) {
    __nv_bfloat16 lo = __float2bfloat16(a);
    __nv_bfloat16 hi = __float2bfloat16(b);
    return (uint32_t)__bfloat16_as_ushort(lo)
         | ((uint32_t)__bfloat16_as_ushort(hi) << 16);
}

#define LDSM4(r0, r1, r2, r3, addr) \
    asm volatile("ldmatrix.sync.aligned.m8n8.x4.shared.b16 {%0,%1,%2,%3}, [%4];" \
                 : "=r"(r0), "=r"(r1), "=r"(r2), "=r"(r3) : "r"(addr))

#define MMA16816(c0, c1, c2, c3, a0, a1, a2, a3, b0, b1) \
    asm volatile("mma.sync.aligned.m16n8k16.row.col.f32.bf16.bf16.f32 " \
                 "{%0,%1,%2,%3}, {%4,%5,%6,%7}, {%8,%9}, {%0,%1,%2,%3};" \
                 : "+f"(c0), "+f"(c1), "+f"(c2), "+f"(c3) \
                 : "r"(a0), "r"(a1), "r"(a2), "r"(a3), "r"(b0), "r"(b1))

// ---------------------------------------------------------------------------
// Tensor-core GEMM: C[32768,1024] = A[32768,256] @ W[256,1024] + bias
// (unchanged from round 10)
// ---------------------------------------------------------------------------
#define GROW 144
#define GOFF_AHI 0
#define GOFF_ALO 18432
#define GOFF_BHI 36864
#define GOFF_BLO 55296
#define GEMM_SMEM 73728

__global__ __launch_bounds__(256, 2) void gemm_tc_kernel(
    const float* __restrict__ x,
    const float* __restrict__ kfw, const float* __restrict__ kbw,
    const float* __restrict__ bfw, const float* __restrict__ bbw,
    int layer)
{
    extern __shared__ unsigned char gsm[];
    const int dir = blockIdx.z;
    const float* __restrict__ A = (layer == 0) ? x : g_out1[dir];
    const float* __restrict__ W = (dir ? kbw : kfw) + layer * 262144;
    const float* __restrict__ bias = (dir ? bbw : bfw) + layer * 1024;
    float* __restrict__ C = g_xz[dir];

    const int m0 = blockIdx.y * 128;
    const int n0 = blockIdx.x * 128;

    const int tid  = threadIdx.x;
    const int lane = tid & 31;
    const int w    = tid >> 5;
    const int wm   = w >> 1;
    const int wn   = w & 1;

    const int aoff = ((lane & 7) + 8 * ((lane >> 3) & 1)) * GROW + 16 * (lane >> 4);
    const int boff = ((lane & 7) + 8 * ((lane >> 4) & 1)) * GROW
                   + 16 * ((lane >> 3) & 1);
    const uint32_t aHiB = smem_u32(gsm + GOFF_AHI) + wm * 32 * GROW + aoff;
    const uint32_t aLoB = smem_u32(gsm + GOFF_ALO) + wm * 32 * GROW + aoff;
    const uint32_t bHiB = smem_u32(gsm + GOFF_BHI) + wn * 64 * GROW + boff;
    const uint32_t bLoB = smem_u32(gsm + GOFF_BLO) + wn * 64 * GROW + boff;

    float c[16][4];
#pragma unroll
    for (int ng = 0; ng < 4; ng++)
#pragma unroll
        for (int h = 0; h < 2; h++) {
            float2 bv = *(const float2*)&bias[n0 + wn * 64 + ng * 16 + h * 8
                                              + 2 * (lane & 3)];
#pragma unroll
            for (int mi = 0; mi < 2; mi++) {
                int f = mi * 8 + 2 * ng + h;
                c[f][0] = bv.x; c[f][1] = bv.y;
                c[f][2] = bv.x; c[f][3] = bv.y;
            }
        }

    for (int kc = 0; kc < 256; kc += 64) {
#pragma unroll
        for (int j = 0; j < 8; j++) {
            int idx = tid + 256 * j;
            int r = idx >> 4, c4 = idx & 15;
            float4 v = *(const float4*)&A[(size_t)(m0 + r) * 256 + kc + c4 * 4];
            __nv_bfloat16 hx = __float2bfloat16(v.x);
            __nv_bfloat16 hy = __float2bfloat16(v.y);
            __nv_bfloat16 hz = __float2bfloat16(v.z);
            __nv_bfloat16 hw = __float2bfloat16(v.w);
            uint2 hi, lo;
            hi.x = ((uint32_t)__bfloat16_as_ushort(hx))
                 | ((uint32_t)__bfloat16_as_ushort(hy) << 16);
            hi.y = ((uint32_t)__bfloat16_as_ushort(hz))
                 | ((uint32_t)__bfloat16_as_ushort(hw) << 16);
            lo.x = bf2pack(v.x - __bfloat162float(hx), v.y - __bfloat162float(hy));
            lo.y = bf2pack(v.z - __bfloat162float(hz), v.w - __bfloat162float(hw));
            *(uint2*)(gsm + GOFF_AHI + r * GROW + c4 * 8) = hi;
            *(uint2*)(gsm + GOFF_ALO + r * GROW + c4 * 8) = lo;
        }
#pragma unroll
        for (int j = 0; j < 8; j++) {
            int idx = tid + 256 * j;
            int k = idx >> 5, n4 = idx & 31;
            float4 v = *(const float4*)&W[(size_t)(kc + k) * 1024 + n0 + n4 * 4];
            float e[4] = {v.x, v.y, v.z, v.w};
#pragma unroll
            for (int q = 0; q < 4; q++) {
                __nv_bfloat16 hb = __float2bfloat16(e[q]);
                __nv_bfloat16 lb = __float2bfloat16(e[q] - __bfloat162float(hb));
                *(__nv_bfloat16*)(gsm + GOFF_BHI + (n4 * 4 + q) * GROW + k * 2) = hb;
                *(__nv_bfloat16*)(gsm + GOFF_BLO + (n4 * 4 + q) * GROW + k * 2) = lb;
            }
        }
        __syncthreads();

#pragma unroll
        for (int ks = 0; ks < 4; ks++) {
            uint32_t ah[2][4], al[2][4];
#pragma unroll
            for (int mi = 0; mi < 2; mi++) {
                LDSM4(ah[mi][0], ah[mi][1], ah[mi][2], ah[mi][3],
                      aHiB + mi * 16 * GROW + 32 * ks);
                LDSM4(al[mi][0], al[mi][1], al[mi][2], al[mi][3],
                      aLoB + mi * 16 * GROW + 32 * ks);
            }
#pragma unroll
            for (int ng = 0; ng < 4; ng++) {
                uint32_t bh[4], bl[4];
                LDSM4(bh[0], bh[1], bh[2], bh[3], bHiB + ng * 16 * GROW + 32 * ks);
                LDSM4(bl[0], bl[1], bl[2], bl[3], bLoB + ng * 16 * GROW + 32 * ks);
#pragma unroll
                for (int mi = 0; mi < 2; mi++) {
                    int f0 = mi * 8 + 2 * ng, f1 = f0 + 1;
                    MMA16816(c[f0][0], c[f0][1], c[f0][2], c[f0][3],
                             ah[mi][0], ah[mi][1], ah[mi][2], ah[mi][3], bh[0], bh[1]);
                    MMA16816(c[f1][0], c[f1][1], c[f1][2], c[f1][3],
                             ah[mi][0], ah[mi][1], ah[mi][2], ah[mi][3], bh[2], bh[3]);
                    MMA16816(c[f0][0], c[f0][1], c[f0][2], c[f0][3],
                             al[mi][0], al[mi][1], al[mi][2], al[mi][3], bh[0], bh[1]);
                    MMA16816(c[f1][0], c[f1][1], c[f1][2], c[f1][3],
                             al[mi][0], al[mi][1], al[mi][2], al[mi][3], bh[2], bh[3]);
                    MMA16816(c[f0][0], c[f0][1], c[f0][2], c[f0][3],
                             ah[mi][0], ah[mi][1], ah[mi][2], ah[mi][3], bl[0], bl[1]);
                    MMA16816(c[f1][0], c[f1][1], c[f1][2], c[f1][3],
                             ah[mi][0], ah[mi][1], ah[mi][2], ah[mi][3], bl[2], bl[3]);
                }
            }
        }
        __syncthreads();
    }

    const int r0 = m0 + wm * 32 + (lane >> 2);
    const int cb = n0 + wn * 64 + 2 * (lane & 3);
#pragma unroll
    for (int mi = 0; mi < 2; mi++)
#pragma unroll
        for (int ni = 0; ni < 8; ni++) {
            int f = mi * 8 + ni;
            int col = cb + ni * 8;
            *(float2*)&C[(size_t)(r0 + mi * 16) * 1024 + col] =
                make_float2(c[f][0], c[f][1]);
            *(float2*)&C[(size_t)(r0 + mi * 16 + 8) * 1024 + col] =
                make_float2(c[f][2], c[f][3]);
        }
}

// ---------------------------------------------------------------------------
// Tensor-core recurrence, 512 threads (16 warps, 4/SMSP), split-K warp pairs.
// 128 CTAs = 2 dirs x 8 batch-tiles x 8 unit-tiles. Warp (wi = w&7, kh = w>>3)
// computes K-steps kh*8..kh*8+7 of tile wi; z partials in 2 SMEM planes,
// summed in the (unchanged, 256-thread) gate phase.
// ---------------------------------------------------------------------------
#define RP 264
#define OFF_RHI 0
#define OFF_RLO 67584
#define OFF_HHI 135168
#define OFF_HLO 143616
#define OFF_Z   152064                  // 2 planes x 2112 floats
#define REC_SMEM_TOTAL (152064 + 16896)

__device__ __forceinline__ void group_barrier(int grp, unsigned* s_sense) {
    __syncthreads();
    if (threadIdx.x == 0) {
        unsigned ls = *s_sense ^ 1u;
        *s_sense = ls;
        __threadfence();
        unsigned v = atomicAdd(&g_cnt[grp], 1u);
        if (v == 7u) {
            g_cnt[grp] = 0u;
            __threadfence();
            g_sns[grp] = ls;
        } else {
            while (g_sns[grp] != ls) { }
        }
    }
    __syncthreads();
}

__global__ __launch_bounds__(512, 1) void rec_mma_kernel(
    const float* __restrict__ rfw, const float* __restrict__ rbw, int layer)
{
    extern __shared__ unsigned char smx[];
    float* zsm = (float*)(smx + OFF_Z);

    const int bx  = blockIdx.x;
    const int dir = bx >> 6;
    const int ut  = bx & 7;
    const int grp = bx >> 3;
    const int bt  = (bx >> 3) & 7;
    const int b0  = bt * 16;
    const int u0  = ut * 32;

    const float* __restrict__ R  = (dir ? rbw : rfw) + layer * 262144;
    const float* __restrict__ xz = g_xz[dir];
    float* __restrict__ outp     = layer ? g_out2[dir] : g_out1[dir];

    const int tid  = threadIdx.x;
    const int lane = tid & 31;
    const int w    = tid >> 5;
    const int wi   = w & 7;             // tile index (as round-10 warp id)
    const int kh   = w >> 3;            // K half (0: ks 0-7, 1: ks 8-15)

    __shared__ unsigned s_sense;
    if (tid == 0) s_sense = g_sns[grp];

    for (int i = tid; i < 128 * 256; i += 512) {
        int ci = i & 127;
        int k  = i >> 7;
        float rv = R[k * 1024 + (ci >> 5) * 256 + u0 + (ci & 31)];
        __nv_bfloat16 hi = __float2bfloat16(rv);
        __nv_bfloat16 lo = __float2bfloat16(rv - __bfloat162float(hi));
        *(__nv_bfloat16*)(smx + OFF_RHI + (ci * RP + k) * 2) = hi;
        *(__nv_bfloat16*)(smx + OFF_RLO + (ci * RP + k) * 2) = lo;
    }

    {
        uint4* dst = (uint4*)g_himg[dir][0][bt];
        for (int i = tid; i < 1056; i += 512) dst[i] = make_uint4(0, 0, 0, 0);
    }
    __threadfence();
    group_barrier(grp, &s_sense);

    const int arow  = (lane & 7) + 8 * ((lane >> 3) & 1);
    const int aoff  = arow * (RP * 2) + 8 * (lane >> 4) * 2;
    const int n0w   = wi * 16;
    const int brow  = n0w + (lane & 7) + 8 * ((lane >> 4) & 1);
    const int boff  = brow * (RP * 2) + 8 * ((lane >> 3) & 1) * 2;
    const uint32_t kbase = kh * 256;    // byte offset of this warp's K half
    const uint32_t aHi = smem_u32(smx + OFF_HHI) + aoff + kbase;
    const uint32_t aLo = smem_u32(smx + OFF_HLO) + aoff + kbase;
    const uint32_t bHi = smem_u32(smx + OFF_RHI) + boff + kbase;
    const uint32_t bLo = smem_u32(smx + OFF_RLO) + boff + kbase;

    const int m_r   = lane >> 2;
    const int ccol  = 2 * (lane & 3);
    const int gcol0 = (wi >> 1) * 256 + u0 + 16 * (wi & 1) + ccol;
    float* zplane   = zsm + kh * 2112;

    // gate phase (tid < 256 only; unchanged from round 10)
    const int gr  = tid >> 4;
    const int gu2 = (tid & 15) * 2;
    float cst[2] = {0.0f, 0.0f};

    for (int s = 0; s < 256; s++) {
        const int t = dir ? (255 - s) : s;

        // C frags: K-half 0 seeds from xz, K-half 1 from zero
        float c0[4], c1[4];
        if (kh == 0) {
            const float* xb = xz + ((size_t)(b0 + m_r) * 256 + t) * 1024 + gcol0;
            const float* xb8 = xb + (size_t)8 * 256 * 1024;
            float2 v00 = *(const float2*)xb;
            float2 v01 = *(const float2*)(xb + 8);
            float2 v10 = *(const float2*)xb8;
            float2 v11 = *(const float2*)(xb8 + 8);
            c0[0] = v00.x; c0[1] = v00.y; c0[2] = v10.x; c0[3] = v10.y;
            c1[0] = v01.x; c1[1] = v01.y; c1[2] = v11.x; c1[3] = v11.y;
        } else {
#pragma unroll
            for (int j = 0; j < 4; j++) { c0[j] = 0.0f; c1[j] = 0.0f; }
        }

        {
            const uint4* src = (const uint4*)g_himg[dir][s & 1][bt];
            uint4* dst = (uint4*)(smx + OFF_HHI);
            for (int i = tid; i < 1056; i += 512) dst[i] = __ldcg(src + i);
        }
        __syncthreads();

        // 8 k-steps for this warp's K half
#pragma unroll 4
        for (int ks = 0; ks < 8; ks++) {
            uint32_t ah0, ah1, ah2, ah3, al0, al1, al2, al3;
            uint32_t bh0, bh1, bh2, bh3, bl0, bl1, bl2, bl3;
            LDSM4(ah0, ah1, ah2, ah3, aHi + 32 * ks);
            LDSM4(bh0, bh1, bh2, bh3, bHi + 32 * ks);
            LDSM4(al0, al1, al2, al3, aLo + 32 * ks);
            LDSM4(bl0, bl1, bl2, bl3, bLo + 32 * ks);
            MMA16816(c0[0], c0[1], c0[2], c0[3], ah0, ah1, ah2, ah3, bh0, bh1);
            MMA16816(c1[0], c1[1], c1[2], c1[3], ah0, ah1, ah2, ah3, bh2, bh3);
            MMA16816(c0[0], c0[1], c0[2], c0[3], al0, al1, al2, al3, bh0, bh1);
            MMA16816(c1[0], c1[1], c1[2], c1[3], al0, al1, al2, al3, bh2, bh3);
            MMA16816(c0[0], c0[1], c0[2], c0[3], ah0, ah1, ah2, ah3, bl0, bl1);
            MMA16816(c1[0], c1[1], c1[2], c1[3], ah0, ah1, ah2, ah3, bl2, bl3);
        }

        {
            int cb = n0w + ccol;
            *(float2*)&zplane[m_r * 132 + cb]       = make_float2(c0[0], c0[1]);
            *(float2*)&zplane[(m_r + 8) * 132 + cb] = make_float2(c0[2], c0[3]);
            *(float2*)&zplane[m_r * 132 + cb + 8]       = make_float2(c1[0], c1[1]);
            *(float2*)&zplane[(m_r + 8) * 132 + cb + 8] = make_float2(c1[2], c1[3]);
        }
        __syncthreads();

        if (tid < 256) {
            unsigned char* img = g_himg[dir][(s + 1) & 1][bt];
            float hv[2];
#pragma unroll
            for (int j = 0; j < 2; j++) {
                int uu = gu2 + j;
                float zi = zsm[gr * 132 + uu]      + zsm[2112 + gr * 132 + uu];
                float zf = zsm[gr * 132 + 32 + uu] + zsm[2112 + gr * 132 + 32 + uu];
                float zg = zsm[gr * 132 + 64 + uu] + zsm[2112 + gr * 132 + 64 + uu];
                float zo = zsm[gr * 132 + 96 + uu] + zsm[2112 + gr * 132 + 96 + uu];
                float ig = sigf(zi);
                float fg = sigf(zf);
                float gg = tanhf_fast(zg);
                float og = sigf(zo);
                float cc = fg * cst[j] + ig * gg;
                cst[j] = cc;
                hv[j] = og * tanhf_fast(cc);
            }
            *(float2*)&outp[((size_t)(b0 + gr) * 256 + t) * 256 + u0 + gu2] =
                make_float2(hv[0], hv[1]);
            __nv_bfloat16 h0 = __float2bfloat16(hv[0]);
            __nv_bfloat16 h1 = __float2bfloat16(hv[1]);
            __nv_bfloat16 l0 = __float2bfloat16(hv[0] - __bfloat162float(h0));
            __nv_bfloat16 l1 = __float2bfloat16(hv[1] - __bfloat162float(h1));
            uint32_t whi = (uint32_t)__bfloat16_as_ushort(h0)
                         | ((uint32_t)__bfloat16_as_ushort(h1) << 16);
            uint32_t wlo = (uint32_t)__bfloat16_as_ushort(l0)
                         | ((uint32_t)__bfloat16_as_ushort(l1) << 16);
            int cidx = u0 + gu2;
            *(uint32_t*)(img + (gr * RP + cidx) * 2)        = whi;
            *(uint32_t*)(img + 8448 + (gr * RP + cidx) * 2) = wlo;
        }

        group_barrier(grp, &s_sense);
    }
}

// ---------------------------------------------------------------------------
// Merge: out = 0.5 * (out2f + out1f + out2b + out1b)  (residual + average)
// ---------------------------------------------------------------------------
__global__ __launch_bounds__(256) void merge_kernel(float4* __restrict__ out) {
    int i = blockIdx.x * blockDim.x + threadIdx.x;
    const float4* a = (const float4*)g_out1[0];
    const float4* b = (const float4*)g_out2[0];
    const float4* c = (const float4*)g_out1[1];
    const float4* d = (const float4*)g_out2[1];
    float4 va = a[i], vb = b[i], vc = c[i], vd = d[i];
    float4 o;
    o.x = 0.5f * (va.x + vb.x + vc.x + vd.x);
    o.y = 0.5f * (va.y + vb.y + vc.y + vd.y);
    o.z = 0.5f * (va.z + vb.z + vc.z + vd.z);
    o.w = 0.5f * (va.w + vb.w + vc.w + vd.w);
    out[i] = o;
}

// ---------------------------------------------------------------------------
extern "C" void kernel_launch(void* const* d_in, const int* in_sizes, int n_in,
                              void* d_out, int out_size) {
    (void)in_sizes; (void)n_in; (void)out_size;
    const float* x   = (const float*)d_in[0];
    const float* kfw = (const float*)d_in[1];
    const float* rfw = (const float*)d_in[2];
    const float* bfw = (const float*)d_in[3];
    const float* kbw = (const float*)d_in[4];
    const float* rbw = (const float*)d_in[5];
    const float* bbw = (const float*)d_in[6];
    float* out = (float*)d_out;

    cudaFuncSetAttribute(rec_mma_kernel,
                         cudaFuncAttributeMaxDynamicSharedMemorySize,
                         REC_SMEM_TOTAL);
    cudaFuncSetAttribute(gemm_tc_kernel,
                         cudaFuncAttributeMaxDynamicSharedMemorySize,
                         GEMM_SMEM);

    dim3 gg(8, 256, 2);
    gemm_tc_kernel<<<gg, 256, GEMM_SMEM>>>(x, kfw, kbw, bfw, bbw, 0);
    rec_mma_kernel<<<128, 512, REC_SMEM_TOTAL>>>(rfw, rbw, 0);
    gemm_tc_kernel<<<gg, 256, GEMM_SMEM>>>(x, kfw, kbw, bfw, bbw, 1);
    rec_mma_kernel<<<128, 512, REC_SMEM_TOTAL>>>(rfw, rbw, 1);
    merge_kernel<<<8192, 256>>>((float4*)out);
}

// round 12
// speedup vs baseline: 1.9377x; 1.1031x over previous
#include <cuda_runtime.h>
#include <cuda_bf16.h>
#include <stdint.h>

// ---------------------------------------------------------------------------
// BiLSTM fp32. Round 12: h exchanged in MMA A-fragment layout so consumers
// LDG fragments directly from L2 into registers (no SMEM staging copy, no
// A-side ldmatrix, one less syncthreads per step). B (R) stays resident in
// SMEM via ldmatrix. Barrier machinery unchanged (proven). GEMM/merge
// unchanged from round 10/11.
// ---------------------------------------------------------------------------

// ---- scratch (device globals; allocation is forbidden) --------------------
__device__ float g_xz[2][33554432];     // [dir][(b*T+t)*1024 + col]
__device__ float g_out1[2][8388608];    // [dir][(b*T+t)*256 + u]
__device__ float g_out2[2][8388608];
// h image in A-fragment layout: [kstep 0..15][lane 0..31][reg 0..3] u32,
// hi plane 8192 B then lo plane 8192 B, per [dir][phase][batch_tile]
__device__ __align__(16) unsigned char g_himg[2][2][8][16384];
__device__ unsigned g_cnt[16];
__device__ volatile unsigned g_sns[16];

__device__ __forceinline__ float sigf(float x) {
    return 1.0f / (1.0f + __expf(-x));
}
__device__ __forceinline__ float tanhf_fast(float x) {
    return 2.0f / (1.0f + __expf(-2.0f * x)) - 1.0f;
}
__device__ __forceinline__ uint32_t smem_u32(const void* p) {
    uint32_t a;
    asm("{ .reg .u64 t; cvta.to.shared.u64 t, %1; cvt.u32.u64 %0, t; }"
        : "=r"(a) : "l"(p));
    return a;
}
__device__ __forceinline__ uint32_t bf2pack(float a, float b) {
    __nv_bfloat16 lo = __float2bfloat16(a);
    __nv_bfloat16 hi = __float2bfloat16(b);
    return (uint32_t)__bfloat16_as_ushort(lo)
         | ((uint32_t)__bfloat16_as_ushort(hi) << 16);
}

#define LDSM4(r0, r1, r2, r3, addr) \
    asm volatile("ldmatrix.sync.aligned.m8n8.x4.shared.b16 {%0,%1,%2,%3}, [%4];" \
                 : "=r"(r0), "=r"(r1), "=r"(r2), "=r"(r3) : "r"(addr))

#define MMA16816(c0, c1, c2, c3, a0, a1, a2, a3, b0, b1) \
    asm volatile("mma.sync.aligned.m16n8k16.row.col.f32.bf16.bf16.f32 " \
                 "{%0,%1,%2,%3}, {%4,%5,%6,%7}, {%8,%9}, {%0,%1,%2,%3};" \
                 : "+f"(c0), "+f"(c1), "+f"(c2), "+f"(c3) \
                 : "r"(a0), "r"(a1), "r"(a2), "r"(a3), "r"(b0), "r"(b1))

// ---------------------------------------------------------------------------
// Tensor-core GEMM: C[32768,1024] = A[32768,256] @ W[256,1024] + bias
// (unchanged from round 10)
// ---------------------------------------------------------------------------
#define GROW 144
#define GOFF_AHI 0
#define GOFF_ALO 18432
#define GOFF_BHI 36864
#define GOFF_BLO 55296
#define GEMM_SMEM 73728

__global__ __launch_bounds__(256, 2) void gemm_tc_kernel(
    const float* __restrict__ x,
    const float* __restrict__ kfw, const float* __restrict__ kbw,
    const float* __restrict__ bfw, const float* __restrict__ bbw,
    int layer)
{
    extern __shared__ unsigned char gsm[];
    const int dir = blockIdx.z;
    const float* __restrict__ A = (layer == 0) ? x : g_out1[dir];
    const float* __restrict__ W = (dir ? kbw : kfw) + layer * 262144;
    const float* __restrict__ bias = (dir ? bbw : bfw) + layer * 1024;
    float* __restrict__ C = g_xz[dir];

    const int m0 = blockIdx.y * 128;
    const int n0 = blockIdx.x * 128;

    const int tid  = threadIdx.x;
    const int lane = tid & 31;
    const int w    = tid >> 5;
    const int wm   = w >> 1;
    const int wn   = w & 1;

    const int aoff = ((lane & 7) + 8 * ((lane >> 3) & 1)) * GROW + 16 * (lane >> 4);
    const int boff = ((lane & 7) + 8 * ((lane >> 4) & 1)) * GROW
                   + 16 * ((lane >> 3) & 1);
    const uint32_t aHiB = smem_u32(gsm + GOFF_AHI) + wm * 32 * GROW + aoff;
    const uint32_t aLoB = smem_u32(gsm + GOFF_ALO) + wm * 32 * GROW + aoff;
    const uint32_t bHiB = smem_u32(gsm + GOFF_BHI) + wn * 64 * GROW + boff;
    const uint32_t bLoB = smem_u32(gsm + GOFF_BLO) + wn * 64 * GROW + boff;

    float c[16][4];
#pragma unroll
    for (int ng = 0; ng < 4; ng++)
#pragma unroll
        for (int h = 0; h < 2; h++) {
            float2 bv = *(const float2*)&bias[n0 + wn * 64 + ng * 16 + h * 8
                                              + 2 * (lane & 3)];
#pragma unroll
            for (int mi = 0; mi < 2; mi++) {
                int f = mi * 8 + 2 * ng + h;
                c[f][0] = bv.x; c[f][1] = bv.y;
                c[f][2] = bv.x; c[f][3] = bv.y;
            }
        }

    for (int kc = 0; kc < 256; kc += 64) {
#pragma unroll
        for (int j = 0; j < 8; j++) {
            int idx = tid + 256 * j;
            int r = idx >> 4, c4 = idx & 15;
            float4 v = *(const float4*)&A[(size_t)(m0 + r) * 256 + kc + c4 * 4];
            __nv_bfloat16 hx = __float2bfloat16(v.x);
            __nv_bfloat16 hy = __float2bfloat16(v.y);
            __nv_bfloat16 hz = __float2bfloat16(v.z);
            __nv_bfloat16 hw = __float2bfloat16(v.w);
            uint2 hi, lo;
            hi.x = ((uint32_t)__bfloat16_as_ushort(hx))
                 | ((uint32_t)__bfloat16_as_ushort(hy) << 16);
            hi.y = ((uint32_t)__bfloat16_as_ushort(hz))
                 | ((uint32_t)__bfloat16_as_ushort(hw) << 16);
            lo.x = bf2pack(v.x - __bfloat162float(hx), v.y - __bfloat162float(hy));
            lo.y = bf2pack(v.z - __bfloat162float(hz), v.w - __bfloat162float(hw));
            *(uint2*)(gsm + GOFF_AHI + r * GROW + c4 * 8) = hi;
            *(uint2*)(gsm + GOFF_ALO + r * GROW + c4 * 8) = lo;
        }
#pragma unroll
        for (int j = 0; j < 8; j++) {
            int idx = tid + 256 * j;
            int k = idx >> 5, n4 = idx & 31;
            float4 v = *(const float4*)&W[(size_t)(kc + k) * 1024 + n0 + n4 * 4];
            float e[4] = {v.x, v.y, v.z, v.w};
#pragma unroll
            for (int q = 0; q < 4; q++) {
                __nv_bfloat16 hb = __float2bfloat16(e[q]);
                __nv_bfloat16 lb = __float2bfloat16(e[q] - __bfloat162float(hb));
                *(__nv_bfloat16*)(gsm + GOFF_BHI + (n4 * 4 + q) * GROW + k * 2) = hb;
                *(__nv_bfloat16*)(gsm + GOFF_BLO + (n4 * 4 + q) * GROW + k * 2) = lb;
            }
        }
        __syncthreads();

#pragma unroll
        for (int ks = 0; ks < 4; ks++) {
            uint32_t ah[2][4], al[2][4];
#pragma unroll
            for (int mi = 0; mi < 2; mi++) {
                LDSM4(ah[mi][0], ah[mi][1], ah[mi][2], ah[mi][3],
                      aHiB + mi * 16 * GROW + 32 * ks);
                LDSM4(al[mi][0], al[mi][1], al[mi][2], al[mi][3],
                      aLoB + mi * 16 * GROW + 32 * ks);
            }
#pragma unroll
            for (int ng = 0; ng < 4; ng++) {
                uint32_t bh[4], bl[4];
                LDSM4(bh[0], bh[1], bh[2], bh[3], bHiB + ng * 16 * GROW + 32 * ks);
                LDSM4(bl[0], bl[1], bl[2], bl[3], bLoB + ng * 16 * GROW + 32 * ks);
#pragma unroll
                for (int mi = 0; mi < 2; mi++) {
                    int f0 = mi * 8 + 2 * ng, f1 = f0 + 1;
                    MMA16816(c[f0][0], c[f0][1], c[f0][2], c[f0][3],
                             ah[mi][0], ah[mi][1], ah[mi][2], ah[mi][3], bh[0], bh[1]);
                    MMA16816(c[f1][0], c[f1][1], c[f1][2], c[f1][3],
                             ah[mi][0], ah[mi][1], ah[mi][2], ah[mi][3], bh[2], bh[3]);
                    MMA16816(c[f0][0], c[f0][1], c[f0][2], c[f0][3],
                             al[mi][0], al[mi][1], al[mi][2], al[mi][3], bh[0], bh[1]);
                    MMA16816(c[f1][0], c[f1][1], c[f1][2], c[f1][3],
                             al[mi][0], al[mi][1], al[mi][2], al[mi][3], bh[2], bh[3]);
                    MMA16816(c[f0][0], c[f0][1], c[f0][2], c[f0][3],
                             ah[mi][0], ah[mi][1], ah[mi][2], ah[mi][3], bl[0], bl[1]);
                    MMA16816(c[f1][0], c[f1][1], c[f1][2], c[f1][3],
                             ah[mi][0], ah[mi][1], ah[mi][2], ah[mi][3], bl[2], bl[3]);
                }
            }
        }
        __syncthreads();
    }

    const int r0 = m0 + wm * 32 + (lane >> 2);
    const int cb = n0 + wn * 64 + 2 * (lane & 3);
#pragma unroll
    for (int mi = 0; mi < 2; mi++)
#pragma unroll
        for (int ni = 0; ni < 8; ni++) {
            int f = mi * 8 + ni;
            int col = cb + ni * 8;
            *(float2*)&C[(size_t)(r0 + mi * 16) * 1024 + col] =
                make_float2(c[f][0], c[f][1]);
            *(float2*)&C[(size_t)(r0 + mi * 16 + 8) * 1024 + col] =
                make_float2(c[f][2], c[f][3]);
        }
}

// ---------------------------------------------------------------------------
// Tensor-core recurrence, 512 threads, split-K warp pairs, A-frags direct
// from global (fragment-layout h image). R (B operand) resident in SMEM.
// 128 CTAs = 2 dirs x 8 batch-tiles x 8 unit-tiles.
// ---------------------------------------------------------------------------
#define RP 264
#define OFF_RHI 0                        // 128*528 = 67584
#define OFF_RLO 67584
#define OFF_Z   135168                   // 2 planes x 2112 floats = 16896 B
#define REC_SMEM_TOTAL (135168 + 16896)

__device__ __forceinline__ void group_barrier(int grp, unsigned* s_sense) {
    __syncthreads();
    if (threadIdx.x == 0) {
        unsigned ls = *s_sense ^ 1u;
        *s_sense = ls;
        __threadfence();
        unsigned v = atomicAdd(&g_cnt[grp], 1u);
        if (v == 7u) {
            g_cnt[grp] = 0u;
            __threadfence();
            g_sns[grp] = ls;
        } else {
            while (g_sns[grp] != ls) { }
        }
    }
    __syncthreads();
}

__global__ __launch_bounds__(512, 1) void rec_mma_kernel(
    const float* __restrict__ rfw, const float* __restrict__ rbw, int layer)
{
    extern __shared__ unsigned char smx[];
    float* zsm = (float*)(smx + OFF_Z);

    const int bx  = blockIdx.x;
    const int dir = bx >> 6;
    const int ut  = bx & 7;
    const int grp = bx >> 3;
    const int bt  = (bx >> 3) & 7;
    const int b0  = bt * 16;
    const int u0  = ut * 32;

    const float* __restrict__ R  = (dir ? rbw : rfw) + layer * 262144;
    const float* __restrict__ xz = g_xz[dir];
    float* __restrict__ outp     = layer ? g_out2[dir] : g_out1[dir];

    const int tid  = threadIdx.x;
    const int lane = tid & 31;
    const int w    = tid >> 5;
    const int wi   = w & 7;             // tile index
    const int kh   = w >> 3;            // K half

    __shared__ unsigned s_sense;
    if (tid == 0) s_sense = g_sns[grp];

    // R slice -> R^T bf16 hi/lo planes (permuted cols), resident
    for (int i = tid; i < 128 * 256; i += 512) {
        int ci = i & 127;
        int k  = i >> 7;
        float rv = R[k * 1024 + (ci >> 5) * 256 + u0 + (ci & 31)];
        __nv_bfloat16 hi = __float2bfloat16(rv);
        __nv_bfloat16 lo = __float2bfloat16(rv - __bfloat162float(hi));
        *(__nv_bfloat16*)(smx + OFF_RHI + (ci * RP + k) * 2) = hi;
        *(__nv_bfloat16*)(smx + OFF_RLO + (ci * RP + k) * 2) = lo;
    }

    // zero phase-0 image (this CTA's 1 KB slice of hi and lo planes)
    {
        unsigned char* img = g_himg[dir][0][bt];
        for (int i = tid; i < 128; i += 512) {
            int pl = i >> 6;                 // plane
            int wd = i & 63;                 // uint4 within 1KB slice
            *(uint4*)(img + pl * 8192 + ut * 1024 + wd * 16) =
                make_uint4(0, 0, 0, 0);
        }
    }
    __threadfence();
    group_barrier(grp, &s_sense);

    // B-side ldmatrix offsets (R)
    const int n0w   = wi * 16;
    const int brow  = n0w + (lane & 7) + 8 * ((lane >> 4) & 1);
    const int boff  = brow * (RP * 2) + 8 * ((lane >> 3) & 1) * 2;
    const uint32_t kbase = kh * 256;
    const uint32_t bHi = smem_u32(smx + OFF_RHI) + boff + kbase;
    const uint32_t bLo = smem_u32(smx + OFF_RLO) + boff + kbase;

    // A-side direct-load address (fragment layout): kstep*512 + lane*16
    const int aoffb = kh * 8 * 512 + lane * 16;

    const int m_r   = lane >> 2;
    const int ccol  = 2 * (lane & 3);
    const int gcol0 = (wi >> 1) * 256 + u0 + 16 * (wi & 1) + ccol;
    float* zplane   = zsm + kh * 2112;

    // gate phase coordinates (tid < 256)
    const int gr  = tid >> 4;
    const int gu2 = (tid & 15) * 2;
    float cst[2] = {0.0f, 0.0f};
    // producer fragment-layout write offset for (gr, u0+gu2, u0+gu2+1)
    const int Ug     = u0 + gu2;
    const int kstepg = Ug >> 4;
    const int jg     = Ug & 15;
    const int lposg  = (jg >> 1) & 3;
    const int regg   = ((jg >> 3) << 1) + (gr >> 3);
    const int pofs   = kstepg * 512 + ((gr & 7) * 4 + lposg) * 16 + regg * 4;

    for (int s = 0; s < 256; s++) {
        const int t = dir ? (255 - s) : s;
        const unsigned char* img_r = g_himg[dir][s & 1][bt];

        // C frags: K-half 0 seeds from xz, K-half 1 from zero
        float c0[4], c1[4];
        if (kh == 0) {
            const float* xb = xz + ((size_t)(b0 + m_r) * 256 + t) * 1024 + gcol0;
            const float* xb8 = xb + (size_t)8 * 256 * 1024;
            float2 v00 = *(const float2*)xb;
            float2 v01 = *(const float2*)(xb + 8);
            float2 v10 = *(const float2*)xb8;
            float2 v11 = *(const float2*)(xb8 + 8);
            c0[0] = v00.x; c0[1] = v00.y; c0[2] = v10.x; c0[3] = v10.y;
            c1[0] = v01.x; c1[1] = v01.y; c1[2] = v11.x; c1[3] = v11.y;
        } else {
#pragma unroll
            for (int j = 0; j < 4; j++) { c0[j] = 0.0f; c1[j] = 0.0f; }
        }

        // software-pipelined: A-frags via direct LDG.128 from L2
        {
            uint4 ahq = __ldcg((const uint4*)(img_r + aoffb));
            uint4 alq = __ldcg((const uint4*)(img_r + 8192 + aoffb));
#pragma unroll
            for (int ks = 0; ks < 8; ks++) {
                uint4 ahn, aln;
                if (ks < 7) {
                    ahn = __ldcg((const uint4*)(img_r + aoffb + (ks + 1) * 512));
                    aln = __ldcg((const uint4*)(img_r + 8192 + aoffb + (ks + 1) * 512));
                }
                uint32_t bh0, bh1, bh2, bh3, bl0, bl1, bl2, bl3;
                LDSM4(bh0, bh1, bh2, bh3, bHi + 32 * ks);
                LDSM4(bl0, bl1, bl2, bl3, bLo + 32 * ks);
                MMA16816(c0[0], c0[1], c0[2], c0[3], ahq.x, ahq.y, ahq.z, ahq.w, bh0, bh1);
                MMA16816(c1[0], c1[1], c1[2], c1[3], ahq.x, ahq.y, ahq.z, ahq.w, bh2, bh3);
                MMA16816(c0[0], c0[1], c0[2], c0[3], alq.x, alq.y, alq.z, alq.w, bh0, bh1);
                MMA16816(c1[0], c1[1], c1[2], c1[3], alq.x, alq.y, alq.z, alq.w, bh2, bh3);
                MMA16816(c0[0], c0[1], c0[2], c0[3], ahq.x, ahq.y, ahq.z, ahq.w, bl0, bl1);
                MMA16816(c1[0], c1[1], c1[2], c1[3], ahq.x, ahq.y, ahq.z, ahq.w, bl2, bl3);
                ahq = ahn; alq = aln;
            }
        }

        // stash z partials
        {
            int cb = n0w + ccol;
            *(float2*)&zplane[m_r * 132 + cb]       = make_float2(c0[0], c0[1]);
            *(float2*)&zplane[(m_r + 8) * 132 + cb] = make_float2(c0[2], c0[3]);
            *(float2*)&zplane[m_r * 132 + cb + 8]       = make_float2(c1[0], c1[1]);
            *(float2*)&zplane[(m_r + 8) * 132 + cb + 8] = make_float2(c1[2], c1[3]);
        }
        __syncthreads();

        if (tid < 256) {
            unsigned char* img_w = g_himg[dir][(s + 1) & 1][bt];
            float hv[2];
#pragma unroll
            for (int j = 0; j < 2; j++) {
                int uu = gu2 + j;
                float zi = zsm[gr * 132 + uu]      + zsm[2112 + gr * 132 + uu];
                float zf = zsm[gr * 132 + 32 + uu] + zsm[2112 + gr * 132 + 32 + uu];
                float zg = zsm[gr * 132 + 64 + uu] + zsm[2112 + gr * 132 + 64 + uu];
                float zo = zsm[gr * 132 + 96 + uu] + zsm[2112 + gr * 132 + 96 + uu];
                float ig = sigf(zi);
                float fg = sigf(zf);
                float gg = tanhf_fast(zg);
                float og = sigf(zo);
                float cc = fg * cst[j] + ig * gg;
                cst[j] = cc;
                hv[j] = og * tanhf_fast(cc);
            }
            *(float2*)&outp[((size_t)(b0 + gr) * 256 + t) * 256 + u0 + gu2] =
                make_float2(hv[0], hv[1]);
            __nv_bfloat16 h0 = __float2bfloat16(hv[0]);
            __nv_bfloat16 h1 = __float2bfloat16(hv[1]);
            __nv_bfloat16 l0 = __float2bfloat16(hv[0] - __bfloat162float(h0));
            __nv_bfloat16 l1 = __float2bfloat16(hv[1] - __bfloat162float(h1));
            uint32_t whi = (uint32_t)__bfloat16_as_ushort(h0)
                         | ((uint32_t)__bfloat16_as_ushort(h1) << 16);
            uint32_t wlo = (uint32_t)__bfloat16_as_ushort(l0)
                         | ((uint32_t)__bfloat16_as_ushort(l1) << 16);
            *(uint32_t*)(img_w + pofs)        = whi;
            *(uint32_t*)(img_w + 8192 + pofs) = wlo;
        }

        group_barrier(grp, &s_sense);
    }
}

// ---------------------------------------------------------------------------
// Merge: out = 0.5 * (out2f + out1f + out2b + out1b)  (residual + average)
// ---------------------------------------------------------------------------
__global__ __launch_bounds__(256) void merge_kernel(float4* __restrict__ out) {
    int i = blockIdx.x * blockDim.x + threadIdx.x;
    const float4* a = (const float4*)g_out1[0];
    const float4* b = (const float4*)g_out2[0];
    const float4* c = (const float4*)g_out1[1];
    const float4* d = (const float4*)g_out2[1];
    float4 va = a[i], vb = b[i], vc = c[i], vd = d[i];
    float4 o;
    o.x = 0.5f * (va.x + vb.x + vc.x + vd.x);
    o.y = 0.5f * (va.y + vb.y + vc.y + vd.y);
    o.z = 0.5f * (va.z + vb.z + vc.z + vd.z);
    o.w = 0.5f * (va.w + vb.w + vc.w + vd.w);
    out[i] = o;
}

// ---------------------------------------------------------------------------
extern "C" void kernel_launch(void* const* d_in, const int* in_sizes, int n_in,
                              void* d_out, int out_size) {
    (void)in_sizes; (void)n_in; (void)out_size;
    const float* x   = (const float*)d_in[0];
    const float* kfw = (const float*)d_in[1];
    const float* rfw = (const float*)d_in[2];
    const float* bfw = (const float*)d_in[3];
    const float* kbw = (const float*)d_in[4];
    const float* rbw = (const float*)d_in[5];
    const float* bbw = (const float*)d_in[6];
    float* out = (float*)d_out;

    cudaFuncSetAttribute(rec_mma_kernel,
                         cudaFuncAttributeMaxDynamicSharedMemorySize,
                         REC_SMEM_TOTAL);
    cudaFuncSetAttribute(gemm_tc_kernel,
                         cudaFuncAttributeMaxDynamicSharedMemorySize,
                         GEMM_SMEM);

    dim3 gg(8, 256, 2);
    gemm_tc_kernel<<<gg, 256, GEMM_SMEM>>>(x, kfw, kbw, bfw, bbw, 0);
    rec_mma_kernel<<<128, 512, REC_SMEM_TOTAL>>>(rfw, rbw, 0);
    gemm_tc_kernel<<<gg, 256, GEMM_SMEM>>>(x, kfw, kbw, bfw, bbw, 1);
    rec_mma_kernel<<<128, 512, REC_SMEM_TOTAL>>>(rfw, rbw, 1);
    merge_kernel<<<8192, 256>>>((float4*)out);
}

// round 13
// speedup vs baseline: 2.0931x; 1.0802x over previous
#include <cuda_runtime.h>
#include <cuda_bf16.h>
#include <stdint.h>

// ---------------------------------------------------------------------------
// BiLSTM fp32. Round 13:
//  - rec: xz C-fragment seeds prefetched one step ahead (register double
//    buffer) so DRAM latency is off the serial recurrence critical path.
//  - gemm: W conversion now writes packed u32 k-pairs (no 2-byte STS).
//  Everything else identical to the 3625us round-12 kernel.
// ---------------------------------------------------------------------------

// ---- scratch (device globals; allocation is forbidden) --------------------
__device__ float g_xz[2][33554432];     // [dir][(b*T+t)*1024 + col]
__device__ float g_out1[2][8388608];    // [dir][(b*T+t)*256 + u]
__device__ float g_out2[2][8388608];
// h image in A-fragment layout: [kstep 0..15][lane 0..31][reg 0..3] u32,
// hi plane 8192 B then lo plane 8192 B, per [dir][phase][batch_tile]
__device__ __align__(16) unsigned char g_himg[2][2][8][16384];
__device__ unsigned g_cnt[16];
__device__ volatile unsigned g_sns[16];

__device__ __forceinline__ float sigf(float x) {
    return 1.0f / (1.0f + __expf(-x));
}
__device__ __forceinline__ float tanhf_fast(float x) {
    return 2.0f / (1.0f + __expf(-2.0f * x)) - 1.0f;
}
__device__ __forceinline__ uint32_t smem_u32(const void* p) {
    uint32_t a;
    asm("{ .reg .u64 t; cvta.to.shared.u64 t, %1; cvt.u32.u64 %0, t; }"
        : "=r"(a) : "l"(p));
    return a;
}
__device__ __forceinline__ uint32_t bf2pack(float a, float b) {
    __nv_bfloat16 lo = __float2bfloat16(a);
    __nv_bfloat16 hi = __float2bfloat16(b);
    return (uint32_t)__bfloat16_as_ushort(lo)
         | ((uint32_t)__bfloat16_as_ushort(hi) << 16);
}

#define LDSM4(r0, r1, r2, r3, addr) \
    asm volatile("ldmatrix.sync.aligned.m8n8.x4.shared.b16 {%0,%1,%2,%3}, [%4];" \
                 : "=r"(r0), "=r"(r1), "=r"(r2), "=r"(r3) : "r"(addr))

#define MMA16816(c0, c1, c2, c3, a0, a1, a2, a3, b0, b1) \
    asm volatile("mma.sync.aligned.m16n8k16.row.col.f32.bf16.bf16.f32 " \
                 "{%0,%1,%2,%3}, {%4,%5,%6,%7}, {%8,%9}, {%0,%1,%2,%3};" \
                 : "+f"(c0), "+f"(c1), "+f"(c2), "+f"(c3) \
                 : "r"(a0), "r"(a1), "r"(a2), "r"(a3), "r"(b0), "r"(b1))

// ---------------------------------------------------------------------------
// Tensor-core GEMM: C[32768,1024] = A[32768,256] @ W[256,1024] + bias
// ---------------------------------------------------------------------------
#define GROW 144
#define GOFF_AHI 0
#define GOFF_ALO 18432
#define GOFF_BHI 36864
#define GOFF_BLO 55296
#define GEMM_SMEM 73728

__global__ __launch_bounds__(256, 2) void gemm_tc_kernel(
    const float* __restrict__ x,
    const float* __restrict__ kfw, const float* __restrict__ kbw,
    const float* __restrict__ bfw, const float* __restrict__ bbw,
    int layer)
{
    extern __shared__ unsigned char gsm[];
    const int dir = blockIdx.z;
    const float* __restrict__ A = (layer == 0) ? x : g_out1[dir];
    const float* __restrict__ W = (dir ? kbw : kfw) + layer * 262144;
    const float* __restrict__ bias = (dir ? bbw : bfw) + layer * 1024;
    float* __restrict__ C = g_xz[dir];

    const int m0 = blockIdx.y * 128;
    const int n0 = blockIdx.x * 128;

    const int tid  = threadIdx.x;
    const int lane = tid & 31;
    const int w    = tid >> 5;
    const int wm   = w >> 1;
    const int wn   = w & 1;

    const int aoff = ((lane & 7) + 8 * ((lane >> 3) & 1)) * GROW + 16 * (lane >> 4);
    const int boff = ((lane & 7) + 8 * ((lane >> 4) & 1)) * GROW
                   + 16 * ((lane >> 3) & 1);
    const uint32_t aHiB = smem_u32(gsm + GOFF_AHI) + wm * 32 * GROW + aoff;
    const uint32_t aLoB = smem_u32(gsm + GOFF_ALO) + wm * 32 * GROW + aoff;
    const uint32_t bHiB = smem_u32(gsm + GOFF_BHI) + wn * 64 * GROW + boff;
    const uint32_t bLoB = smem_u32(gsm + GOFF_BLO) + wn * 64 * GROW + boff;

    float c[16][4];
#pragma unroll
    for (int ng = 0; ng < 4; ng++)
#pragma unroll
        for (int h = 0; h < 2; h++) {
            float2 bv = *(const float2*)&bias[n0 + wn * 64 + ng * 16 + h * 8
                                              + 2 * (lane & 3)];
#pragma unroll
            for (int mi = 0; mi < 2; mi++) {
                int f = mi * 8 + 2 * ng + h;
                c[f][0] = bv.x; c[f][1] = bv.y;
                c[f][2] = bv.x; c[f][3] = bv.y;
            }
        }

    for (int kc = 0; kc < 256; kc += 64) {
        // --- A chunk [128 m][64 k] -> bf16 hi/lo, packed uint2 stores ---
#pragma unroll
        for (int j = 0; j < 8; j++) {
            int idx = tid + 256 * j;
            int r = idx >> 4, c4 = idx & 15;
            float4 v = *(const float4*)&A[(size_t)(m0 + r) * 256 + kc + c4 * 4];
            __nv_bfloat16 hx = __float2bfloat16(v.x);
            __nv_bfloat16 hy = __float2bfloat16(v.y);
            __nv_bfloat16 hz = __float2bfloat16(v.z);
            __nv_bfloat16 hw = __float2bfloat16(v.w);
            uint2 hi, lo;
            hi.x = ((uint32_t)__bfloat16_as_ushort(hx))
                 | ((uint32_t)__bfloat16_as_ushort(hy) << 16);
            hi.y = ((uint32_t)__bfloat16_as_ushort(hz))
                 | ((uint32_t)__bfloat16_as_ushort(hw) << 16);
            lo.x = bf2pack(v.x - __bfloat162float(hx), v.y - __bfloat162float(hy));
            lo.y = bf2pack(v.z - __bfloat162float(hz), v.w - __bfloat162float(hw));
            *(uint2*)(gsm + GOFF_AHI + r * GROW + c4 * 8) = hi;
            *(uint2*)(gsm + GOFF_ALO + r * GROW + c4 * 8) = lo;
        }
        // --- W chunk [64 k][128 n] -> B^T [n][k], packed u32 (k-pair) stores
#pragma unroll
        for (int j = 0; j < 4; j++) {
            int p  = tid + 256 * j;          // pair index (4096 total)
            int k2 = p >> 5;                 // k pair 0..31 -> k = 2*k2
            int n4 = p & 31;                 // n group -> n = 4*n4
            float4 v0 = *(const float4*)&W[(size_t)(kc + 2 * k2) * 1024 + n0 + n4 * 4];
            float4 v1 = *(const float4*)&W[(size_t)(kc + 2 * k2 + 1) * 1024 + n0 + n4 * 4];
            float e0[4] = {v0.x, v0.y, v0.z, v0.w};
            float e1[4] = {v1.x, v1.y, v1.z, v1.w};
#pragma unroll
            for (int q = 0; q < 4; q++) {
                __nv_bfloat16 h0 = __float2bfloat16(e0[q]);
                __nv_bfloat16 h1 = __float2bfloat16(e1[q]);
                uint32_t whi = (uint32_t)__bfloat16_as_ushort(h0)
                             | ((uint32_t)__bfloat16_as_ushort(h1) << 16);
                uint32_t wlo = bf2pack(e0[q] - __bfloat162float(h0),
                                       e1[q] - __bfloat162float(h1));
                int nn = n4 * 4 + q;
                *(uint32_t*)(gsm + GOFF_BHI + nn * GROW + k2 * 4) = whi;
                *(uint32_t*)(gsm + GOFF_BLO + nn * GROW + k2 * 4) = wlo;
            }
        }
        __syncthreads();

#pragma unroll
        for (int ks = 0; ks < 4; ks++) {
            uint32_t ah[2][4], al[2][4];
#pragma unroll
            for (int mi = 0; mi < 2; mi++) {
                LDSM4(ah[mi][0], ah[mi][1], ah[mi][2], ah[mi][3],
                      aHiB + mi * 16 * GROW + 32 * ks);
                LDSM4(al[mi][0], al[mi][1], al[mi][2], al[mi][3],
                      aLoB + mi * 16 * GROW + 32 * ks);
            }
#pragma unroll
            for (int ng = 0; ng < 4; ng++) {
                uint32_t bh[4], bl[4];
                LDSM4(bh[0], bh[1], bh[2], bh[3], bHiB + ng * 16 * GROW + 32 * ks);
                LDSM4(bl[0], bl[1], bl[2], bl[3], bLoB + ng * 16 * GROW + 32 * ks);
#pragma unroll
                for (int mi = 0; mi < 2; mi++) {
                    int f0 = mi * 8 + 2 * ng, f1 = f0 + 1;
                    MMA16816(c[f0][0], c[f0][1], c[f0][2], c[f0][3],
                             ah[mi][0], ah[mi][1], ah[mi][2], ah[mi][3], bh[0], bh[1]);
                    MMA16816(c[f1][0], c[f1][1], c[f1][2], c[f1][3],
                             ah[mi][0], ah[mi][1], ah[mi][2], ah[mi][3], bh[2], bh[3]);
                    MMA16816(c[f0][0], c[f0][1], c[f0][2], c[f0][3],
                             al[mi][0], al[mi][1], al[mi][2], al[mi][3], bh[0], bh[1]);
                    MMA16816(c[f1][0], c[f1][1], c[f1][2], c[f1][3],
                             al[mi][0], al[mi][1], al[mi][2], al[mi][3], bh[2], bh[3]);
                    MMA16816(c[f0][0], c[f0][1], c[f0][2], c[f0][3],
                             ah[mi][0], ah[mi][1], ah[mi][2], ah[mi][3], bl[0], bl[1]);
                    MMA16816(c[f1][0], c[f1][1], c[f1][2], c[f1][3],
                             ah[mi][0], ah[mi][1], ah[mi][2], ah[mi][3], bl[2], bl[3]);
                }
            }
        }
        __syncthreads();
    }

    const int r0 = m0 + wm * 32 + (lane >> 2);
    const int cb = n0 + wn * 64 + 2 * (lane & 3);
#pragma unroll
    for (int mi = 0; mi < 2; mi++)
#pragma unroll
        for (int ni = 0; ni < 8; ni++) {
            int f = mi * 8 + ni;
            int col = cb + ni * 8;
            *(float2*)&C[(size_t)(r0 + mi * 16) * 1024 + col] =
                make_float2(c[f][0], c[f][1]);
            *(float2*)&C[(size_t)(r0 + mi * 16 + 8) * 1024 + col] =
                make_float2(c[f][2], c[f][3]);
        }
}

// ---------------------------------------------------------------------------
// Tensor-core recurrence, 512 threads, split-K warp pairs, A-frags direct
// from global (fragment-layout h image). xz seeds prefetched 1 step ahead.
// ---------------------------------------------------------------------------
#define RP 264
#define OFF_RHI 0
#define OFF_RLO 67584
#define OFF_Z   135168
#define REC_SMEM_TOTAL (135168 + 16896)

__device__ __forceinline__ void group_barrier(int grp, unsigned* s_sense) {
    __syncthreads();
    if (threadIdx.x == 0) {
        unsigned ls = *s_sense ^ 1u;
        *s_sense = ls;
        __threadfence();
        unsigned v = atomicAdd(&g_cnt[grp], 1u);
        if (v == 7u) {
            g_cnt[grp] = 0u;
            __threadfence();
            g_sns[grp] = ls;
        } else {
            while (g_sns[grp] != ls) { }
        }
    }
    __syncthreads();
}

__global__ __launch_bounds__(512, 1) void rec_mma_kernel(
    const float* __restrict__ rfw, const float* __restrict__ rbw, int layer)
{
    extern __shared__ unsigned char smx[];
    float* zsm = (float*)(smx + OFF_Z);

    const int bx  = blockIdx.x;
    const int dir = bx >> 6;
    const int ut  = bx & 7;
    const int grp = bx >> 3;
    const int bt  = (bx >> 3) & 7;
    const int b0  = bt * 16;
    const int u0  = ut * 32;

    const float* __restrict__ R  = (dir ? rbw : rfw) + layer * 262144;
    const float* __restrict__ xz = g_xz[dir];
    float* __restrict__ outp     = layer ? g_out2[dir] : g_out1[dir];

    const int tid  = threadIdx.x;
    const int lane = tid & 31;
    const int w    = tid >> 5;
    const int wi   = w & 7;
    const int kh   = w >> 3;

    __shared__ unsigned s_sense;
    if (tid == 0) s_sense = g_sns[grp];

    for (int i = tid; i < 128 * 256; i += 512) {
        int ci = i & 127;
        int k  = i >> 7;
        float rv = R[k * 1024 + (ci >> 5) * 256 + u0 + (ci & 31)];
        __nv_bfloat16 hi = __float2bfloat16(rv);
        __nv_bfloat16 lo = __float2bfloat16(rv - __bfloat162float(hi));
        *(__nv_bfloat16*)(smx + OFF_RHI + (ci * RP + k) * 2) = hi;
        *(__nv_bfloat16*)(smx + OFF_RLO + (ci * RP + k) * 2) = lo;
    }

    {
        unsigned char* img = g_himg[dir][0][bt];
        for (int i = tid; i < 128; i += 512) {
            int pl = i >> 6;
            int wd = i & 63;
            *(uint4*)(img + pl * 8192 + ut * 1024 + wd * 16) =
                make_uint4(0, 0, 0, 0);
        }
    }
    __threadfence();
    group_barrier(grp, &s_sense);

    const int n0w   = wi * 16;
    const int brow  = n0w + (lane & 7) + 8 * ((lane >> 4) & 1);
    const int boff  = brow * (RP * 2) + 8 * ((lane >> 3) & 1) * 2;
    const uint32_t kbase = kh * 256;
    const uint32_t bHi = smem_u32(smx + OFF_RHI) + boff + kbase;
    const uint32_t bLo = smem_u32(smx + OFF_RLO) + boff + kbase;

    const int aoffb = kh * 8 * 512 + lane * 16;

    const int m_r   = lane >> 2;
    const int ccol  = 2 * (lane & 3);
    const int gcol0 = (wi >> 1) * 256 + u0 + 16 * (wi & 1) + ccol;
    float* zplane   = zsm + kh * 2112;

    const int gr  = tid >> 4;
    const int gu2 = (tid & 15) * 2;
    float cst[2] = {0.0f, 0.0f};
    const int Ug     = u0 + gu2;
    const int kstepg = Ug >> 4;
    const int jg     = Ug & 15;
    const int lposg  = (jg >> 1) & 3;
    const int regg   = ((jg >> 3) << 1) + (gr >> 3);
    const int pofs   = kstepg * 512 + ((gr & 7) * 4 + lposg) * 16 + regg * 4;

    // ---- xz prefetch buffer (step 0) ----
    float xzn[8];
    if (kh == 0) {
        const int t0 = dir ? 255 : 0;
        const float* xb = xz + ((size_t)(b0 + m_r) * 256 + t0) * 1024 + gcol0;
        const float* xb8 = xb + (size_t)8 * 256 * 1024;
        float2 v00 = *(const float2*)xb;
        float2 v01 = *(const float2*)(xb + 8);
        float2 v10 = *(const float2*)xb8;
        float2 v11 = *(const float2*)(xb8 + 8);
        xzn[0] = v00.x; xzn[1] = v00.y; xzn[2] = v10.x; xzn[3] = v10.y;
        xzn[4] = v01.x; xzn[5] = v01.y; xzn[6] = v11.x; xzn[7] = v11.y;
    }

    for (int s = 0; s < 256; s++) {
        const int t = dir ? (255 - s) : s;
        const unsigned char* img_r = g_himg[dir][s & 1][bt];

        // C frags from prefetched xz (kh==0) or zero (kh==1)
        float c0[4], c1[4];
        if (kh == 0) {
            c0[0] = xzn[0]; c0[1] = xzn[1]; c0[2] = xzn[2]; c0[3] = xzn[3];
            c1[0] = xzn[4]; c1[1] = xzn[5]; c1[2] = xzn[6]; c1[3] = xzn[7];
            // prefetch for step s+1 (full step of slack for DRAM)
            int sn = (s < 255) ? (s + 1) : s;
            int tn = dir ? (255 - sn) : sn;
            const float* xb = xz + ((size_t)(b0 + m_r) * 256 + tn) * 1024 + gcol0;
            const float* xb8 = xb + (size_t)8 * 256 * 1024;
            float2 v00 = *(const float2*)xb;
            float2 v01 = *(const float2*)(xb + 8);
            float2 v10 = *(const float2*)xb8;
            float2 v11 = *(const float2*)(xb8 + 8);
            xzn[0] = v00.x; xzn[1] = v00.y; xzn[2] = v10.x; xzn[3] = v10.y;
            xzn[4] = v01.x; xzn[5] = v01.y; xzn[6] = v11.x; xzn[7] = v11.y;
        } else {
#pragma unroll
            for (int j = 0; j < 4; j++) { c0[j] = 0.0f; c1[j] = 0.0f; }
        }

        // software-pipelined MMA: A-frags via direct LDG.128 from L2
        {
            uint4 ahq = __ldcg((const uint4*)(img_r + aoffb));
            uint4 alq = __ldcg((const uint4*)(img_r + 8192 + aoffb));
#pragma unroll
            for (int ks = 0; ks < 8; ks++) {
                uint4 ahn, aln;
                if (ks < 7) {
                    ahn = __ldcg((const uint4*)(img_r + aoffb + (ks + 1) * 512));
                    aln = __ldcg((const uint4*)(img_r + 8192 + aoffb + (ks + 1) * 512));
                }
                uint32_t bh0, bh1, bh2, bh3, bl0, bl1, bl2, bl3;
                LDSM4(bh0, bh1, bh2, bh3, bHi + 32 * ks);
                LDSM4(bl0, bl1, bl2, bl3, bLo + 32 * ks);
                MMA16816(c0[0], c0[1], c0[2], c0[3], ahq.x, ahq.y, ahq.z, ahq.w, bh0, bh1);
                MMA16816(c1[0], c1[1], c1[2], c1[3], ahq.x, ahq.y, ahq.z, ahq.w, bh2, bh3);
                MMA16816(c0[0], c0[1], c0[2], c0[3], alq.x, alq.y, alq.z, alq.w, bh0, bh1);
                MMA16816(c1[0], c1[1], c1[2], c1[3], alq.x, alq.y, alq.z, alq.w, bh2, bh3);
                MMA16816(c0[0], c0[1], c0[2], c0[3], ahq.x, ahq.y, ahq.z, ahq.w, bl0, bl1);
                MMA16816(c1[0], c1[1], c1[2], c1[3], ahq.x, ahq.y, ahq.z, ahq.w, bl2, bl3);
                ahq = ahn; alq = aln;
            }
        }

        {
            int cb = n0w + ccol;
            *(float2*)&zplane[m_r * 132 + cb]       = make_float2(c0[0], c0[1]);
            *(float2*)&zplane[(m_r + 8) * 132 + cb] = make_float2(c0[2], c0[3]);
            *(float2*)&zplane[m_r * 132 + cb + 8]       = make_float2(c1[0], c1[1]);
            *(float2*)&zplane[(m_r + 8) * 132 + cb + 8] = make_float2(c1[2], c1[3]);
        }
        __syncthreads();

        if (tid < 256) {
            unsigned char* img_w = g_himg[dir][(s + 1) & 1][bt];
            float hv[2];
#pragma unroll
            for (int j = 0; j < 2; j++) {
                int uu = gu2 + j;
                float zi = zsm[gr * 132 + uu]      + zsm[2112 + gr * 132 + uu];
                float zf = zsm[gr * 132 + 32 + uu] + zsm[2112 + gr * 132 + 32 + uu];
                float zg = zsm[gr * 132 + 64 + uu] + zsm[2112 + gr * 132 + 64 + uu];
                float zo = zsm[gr * 132 + 96 + uu] + zsm[2112 + gr * 132 + 96 + uu];
                float ig = sigf(zi);
                float fg = sigf(zf);
                float gg = tanhf_fast(zg);
                float og = sigf(zo);
                float cc = fg * cst[j] + ig * gg;
                cst[j] = cc;
                hv[j] = og * tanhf_fast(cc);
            }
            *(float2*)&outp[((size_t)(b0 + gr) * 256 + t) * 256 + u0 + gu2] =
                make_float2(hv[0], hv[1]);
            __nv_bfloat16 h0 = __float2bfloat16(hv[0]);
            __nv_bfloat16 h1 = __float2bfloat16(hv[1]);
            __nv_bfloat16 l0 = __float2bfloat16(hv[0] - __bfloat162float(h0));
            __nv_bfloat16 l1 = __float2bfloat16(hv[1] - __bfloat162float(h1));
            uint32_t whi = (uint32_t)__bfloat16_as_ushort(h0)
                         | ((uint32_t)__bfloat16_as_ushort(h1) << 16);
            uint32_t wlo = (uint32_t)__bfloat16_as_ushort(l0)
                         | ((uint32_t)__bfloat16_as_ushort(l1) << 16);
            *(uint32_t*)(img_w + pofs)        = whi;
            *(uint32_t*)(img_w + 8192 + pofs) = wlo;
        }

        group_barrier(grp, &s_sense);
    }
}

// ---------------------------------------------------------------------------
// Merge: out = 0.5 * (out2f + out1f + out2b + out1b)  (residual + average)
// ---------------------------------------------------------------------------
__global__ __launch_bounds__(256) void merge_kernel(float4* __restrict__ out) {
    int i = blockIdx.x * blockDim.x + threadIdx.x;
    const float4* a = (const float4*)g_out1[0];
    const float4* b = (const float4*)g_out2[0];
    const float4* c = (const float4*)g_out1[1];
    const float4* d = (const float4*)g_out2[1];
    float4 va = a[i], vb = b[i], vc = c[i], vd = d[i];
    float4 o;
    o.x = 0.5f * (va.x + vb.x + vc.x + vd.x);
    o.y = 0.5f * (va.y + vb.y + vc.y + vd.y);
    o.z = 0.5f * (va.z + vb.z + vc.z + vd.z);
    o.w = 0.5f * (va.w + vb.w + vc.w + vd.w);
    out[i] = o;
}

// ---------------------------------------------------------------------------
extern "C" void kernel_launch(void* const* d_in, const int* in_sizes, int n_in,
                              void* d_out, int out_size) {
    (void)in_sizes; (void)n_in; (void)out_size;
    const float* x   = (const float*)d_in[0];
    const float* kfw = (const float*)d_in[1];
    const float* rfw = (const float*)d_in[2];
    const float* bfw = (const float*)d_in[3];
    const float* kbw = (const float*)d_in[4];
    const float* rbw = (const float*)d_in[5];
    const float* bbw = (const float*)d_in[6];
    float* out = (float*)d_out;

    cudaFuncSetAttribute(rec_mma_kernel,
                         cudaFuncAttributeMaxDynamicSharedMemorySize,
                         REC_SMEM_TOTAL);
    cudaFuncSetAttribute(gemm_tc_kernel,
                         cudaFuncAttributeMaxDynamicSharedMemorySize,
                         GEMM_SMEM);

    dim3 gg(8, 256, 2);
    gemm_tc_kernel<<<gg, 256, GEMM_SMEM>>>(x, kfw, kbw, bfw, bbw, 0);
    rec_mma_kernel<<<128, 512, REC_SMEM_TOTAL>>>(rfw, rbw, 0);
    gemm_tc_kernel<<<gg, 256, GEMM_SMEM>>>(x, kfw, kbw, bfw, bbw, 1);
    rec_mma_kernel<<<128, 512, REC_SMEM_TOTAL>>>(rfw, rbw, 1);
    merge_kernel<<<8192, 256>>>((float4*)out);
}

// round 15
// speedup vs baseline: 2.1668x; 1.0352x over previous
#include <cuda_runtime.h>
#include <cuda_bf16.h>
#include <stdint.h>

// ---------------------------------------------------------------------------
// BiLSTM fp32. Round 15 = proven-parts recombination:
//  - rec: round-12 version verbatim (atomic sense-reversing barrier, no xz
//    prefetch) — measured 1134 us/launch. Round-14 flag barrier reverted
//    (correctness failure).
//  - gemm: round-13 version (packed-u32 W conversion) — measured ~510 us.
// ---------------------------------------------------------------------------

// ---- scratch (device globals; allocation is forbidden) --------------------
__device__ float g_xz[2][33554432];     // [dir][(b*T+t)*1024 + col]
__device__ float g_out1[2][8388608];    // [dir][(b*T+t)*256 + u]
__device__ float g_out2[2][8388608];
// h image in A-fragment layout: [kstep 0..15][lane 0..31][reg 0..3] u32,
// hi plane 8192 B then lo plane 8192 B, per [dir][phase][batch_tile]
__device__ __align__(16) unsigned char g_himg[2][2][8][16384];
__device__ unsigned g_cnt[16];
__device__ volatile unsigned g_sns[16];

__device__ __forceinline__ float sigf(float x) {
    return 1.0f / (1.0f + __expf(-x));
}
__device__ __forceinline__ float tanhf_fast(float x) {
    return 2.0f / (1.0f + __expf(-2.0f * x)) - 1.0f;
}
__device__ __forceinline__ uint32_t smem_u32(const void* p) {
    uint32_t a;
    asm("{ .reg .u64 t; cvta.to.shared.u64 t, %1; cvt.u32.u64 %0, t; }"
        : "=r"(a) : "l"(p));
    return a;
}
__device__ __forceinline__ uint32_t bf2pack(float a, float b) {
    __nv_bfloat16 lo = __float2bfloat16(a);
    __nv_bfloat16 hi = __float2bfloat16(b);
    return (uint32_t)__bfloat16_as_ushort(lo)
         | ((uint32_t)__bfloat16_as_ushort(hi) << 16);
}

#define LDSM4(r0, r1, r2, r3, addr) \
    asm volatile("ldmatrix.sync.aligned.m8n8.x4.shared.b16 {%0,%1,%2,%3}, [%4];" \
                 : "=r"(r0), "=r"(r1), "=r"(r2), "=r"(r3) : "r"(addr))

#define MMA16816(c0, c1, c2, c3, a0, a1, a2, a3, b0, b1) \
    asm volatile("mma.sync.aligned.m16n8k16.row.col.f32.bf16.bf16.f32 " \
                 "{%0,%1,%2,%3}, {%4,%5,%6,%7}, {%8,%9}, {%0,%1,%2,%3};" \
                 : "+f"(c0), "+f"(c1), "+f"(c2), "+f"(c3) \
                 : "r"(a0), "r"(a1), "r"(a2), "r"(a3), "r"(b0), "r"(b1))

// ---------------------------------------------------------------------------
// Tensor-core GEMM: C[32768,1024] = A[32768,256] @ W[256,1024] + bias
// (round-13 version)
// ---------------------------------------------------------------------------
#define GROW 144
#define GOFF_AHI 0
#define GOFF_ALO 18432
#define GOFF_BHI 36864
#define GOFF_BLO 55296
#define GEMM_SMEM 73728

__global__ __launch_bounds__(256, 2) void gemm_tc_kernel(
    const float* __restrict__ x,
    const float* __restrict__ kfw, const float* __restrict__ kbw,
    const float* __restrict__ bfw, const float* __restrict__ bbw,
    int layer)
{
    extern __shared__ unsigned char gsm[];
    const int dir = blockIdx.z;
    const float* __restrict__ A = (layer == 0) ? x : g_out1[dir];
    const float* __restrict__ W = (dir ? kbw : kfw) + layer * 262144;
    const float* __restrict__ bias = (dir ? bbw : bfw) + layer * 1024;
    float* __restrict__ C = g_xz[dir];

    const int m0 = blockIdx.y * 128;
    const int n0 = blockIdx.x * 128;

    const int tid  = threadIdx.x;
    const int lane = tid & 31;
    const int w    = tid >> 5;
    const int wm   = w >> 1;
    const int wn   = w & 1;

    const int aoff = ((lane & 7) + 8 * ((lane >> 3) & 1)) * GROW + 16 * (lane >> 4);
    const int boff = ((lane & 7) + 8 * ((lane >> 4) & 1)) * GROW
                   + 16 * ((lane >> 3) & 1);
    const uint32_t aHiB = smem_u32(gsm + GOFF_AHI) + wm * 32 * GROW + aoff;
    const uint32_t aLoB = smem_u32(gsm + GOFF_ALO) + wm * 32 * GROW + aoff;
    const uint32_t bHiB = smem_u32(gsm + GOFF_BHI) + wn * 64 * GROW + boff;
    const uint32_t bLoB = smem_u32(gsm + GOFF_BLO) + wn * 64 * GROW + boff;

    float c[16][4];
#pragma unroll
    for (int ng = 0; ng < 4; ng++)
#pragma unroll
        for (int h = 0; h < 2; h++) {
            float2 bv = *(const float2*)&bias[n0 + wn * 64 + ng * 16 + h * 8
                                              + 2 * (lane & 3)];
#pragma unroll
            for (int mi = 0; mi < 2; mi++) {
                int f = mi * 8 + 2 * ng + h;
                c[f][0] = bv.x; c[f][1] = bv.y;
                c[f][2] = bv.x; c[f][3] = bv.y;
            }
        }

    for (int kc = 0; kc < 256; kc += 64) {
        // --- A chunk [128 m][64 k] -> bf16 hi/lo, packed uint2 stores ---
#pragma unroll
        for (int j = 0; j < 8; j++) {
            int idx = tid + 256 * j;
            int r = idx >> 4, c4 = idx & 15;
            float4 v = *(const float4*)&A[(size_t)(m0 + r) * 256 + kc + c4 * 4];
            __nv_bfloat16 hx = __float2bfloat16(v.x);
            __nv_bfloat16 hy = __float2bfloat16(v.y);
            __nv_bfloat16 hz = __float2bfloat16(v.z);
            __nv_bfloat16 hw = __float2bfloat16(v.w);
            uint2 hi, lo;
            hi.x = ((uint32_t)__bfloat16_as_ushort(hx))
                 | ((uint32_t)__bfloat16_as_ushort(hy) << 16);
            hi.y = ((uint32_t)__bfloat16_as_ushort(hz))
                 | ((uint32_t)__bfloat16_as_ushort(hw) << 16);
            lo.x = bf2pack(v.x - __bfloat162float(hx), v.y - __bfloat162float(hy));
            lo.y = bf2pack(v.z - __bfloat162float(hz), v.w - __bfloat162float(hw));
            *(uint2*)(gsm + GOFF_AHI + r * GROW + c4 * 8) = hi;
            *(uint2*)(gsm + GOFF_ALO + r * GROW + c4 * 8) = lo;
        }
        // --- W chunk [64 k][128 n] -> B^T [n][k], packed u32 (k-pair) stores
#pragma unroll
        for (int j = 0; j < 4; j++) {
            int p  = tid + 256 * j;
            int k2 = p >> 5;
            int n4 = p & 31;
            float4 v0 = *(const float4*)&W[(size_t)(kc + 2 * k2) * 1024 + n0 + n4 * 4];
            float4 v1 = *(const float4*)&W[(size_t)(kc + 2 * k2 + 1) * 1024 + n0 + n4 * 4];
            float e0[4] = {v0.x, v0.y, v0.z, v0.w};
            float e1[4] = {v1.x, v1.y, v1.z, v1.w};
#pragma unroll
            for (int q = 0; q < 4; q++) {
                __nv_bfloat16 h0 = __float2bfloat16(e0[q]);
                __nv_bfloat16 h1 = __float2bfloat16(e1[q]);
                uint32_t whi = (uint32_t)__bfloat16_as_ushort(h0)
                             | ((uint32_t)__bfloat16_as_ushort(h1) << 16);
                uint32_t wlo = bf2pack(e0[q] - __bfloat162float(h0),
                                       e1[q] - __bfloat162float(h1));
                int nn = n4 * 4 + q;
                *(uint32_t*)(gsm + GOFF_BHI + nn * GROW + k2 * 4) = whi;
                *(uint32_t*)(gsm + GOFF_BLO + nn * GROW + k2 * 4) = wlo;
            }
        }
        __syncthreads();

#pragma unroll
        for (int ks = 0; ks < 4; ks++) {
            uint32_t ah[2][4], al[2][4];
#pragma unroll
            for (int mi = 0; mi < 2; mi++) {
                LDSM4(ah[mi][0], ah[mi][1], ah[mi][2], ah[mi][3],
                      aHiB + mi * 16 * GROW + 32 * ks);
                LDSM4(al[mi][0], al[mi][1], al[mi][2], al[mi][3],
                      aLoB + mi * 16 * GROW + 32 * ks);
            }
#pragma unroll
            for (int ng = 0; ng < 4; ng++) {
                uint32_t bh[4], bl[4];
                LDSM4(bh[0], bh[1], bh[2], bh[3], bHiB + ng * 16 * GROW + 32 * ks);
                LDSM4(bl[0], bl[1], bl[2], bl[3], bLoB + ng * 16 * GROW + 32 * ks);
#pragma unroll
                for (int mi = 0; mi < 2; mi++) {
                    int f0 = mi * 8 + 2 * ng, f1 = f0 + 1;
                    MMA16816(c[f0][0], c[f0][1], c[f0][2], c[f0][3],
                             ah[mi][0], ah[mi][1], ah[mi][2], ah[mi][3], bh[0], bh[1]);
                    MMA16816(c[f1][0], c[f1][1], c[f1][2], c[f1][3],
                             ah[mi][0], ah[mi][1], ah[mi][2], ah[mi][3], bh[2], bh[3]);
                    MMA16816(c[f0][0], c[f0][1], c[f0][2], c[f0][3],
                             al[mi][0], al[mi][1], al[mi][2], al[mi][3], bh[0], bh[1]);
                    MMA16816(c[f1][0], c[f1][1], c[f1][2], c[f1][3],
                             al[mi][0], al[mi][1], al[mi][2], al[mi][3], bh[2], bh[3]);
                    MMA16816(c[f0][0], c[f0][1], c[f0][2], c[f0][3],
                             ah[mi][0], ah[mi][1], ah[mi][2], ah[mi][3], bl[0], bl[1]);
                    MMA16816(c[f1][0], c[f1][1], c[f1][2], c[f1][3],
                             ah[mi][0], ah[mi][1], ah[mi][2], ah[mi][3], bl[2], bl[3]);
                }
            }
        }
        __syncthreads();
    }

    const int r0 = m0 + wm * 32 + (lane >> 2);
    const int cb = n0 + wn * 64 + 2 * (lane & 3);
#pragma unroll
    for (int mi = 0; mi < 2; mi++)
#pragma unroll
        for (int ni = 0; ni < 8; ni++) {
            int f = mi * 8 + ni;
            int col = cb + ni * 8;
            *(float2*)&C[(size_t)(r0 + mi * 16) * 1024 + col] =
                make_float2(c[f][0], c[f][1]);
            *(float2*)&C[(size_t)(r0 + mi * 16 + 8) * 1024 + col] =
                make_float2(c[f][2], c[f][3]);
        }
}

// ---------------------------------------------------------------------------
// Tensor-core recurrence (round-12 version verbatim): 512 threads, split-K
// warp pairs, A-frags direct from global (fragment-layout h image), atomic
// sense-reversing per-step barrier.
// ---------------------------------------------------------------------------
#define RP 264
#define OFF_RHI 0
#define OFF_RLO 67584
#define OFF_Z   135168
#define REC_SMEM_TOTAL (135168 + 16896)

__device__ __forceinline__ void group_barrier(int grp, unsigned* s_sense) {
    __syncthreads();
    if (threadIdx.x == 0) {
        unsigned ls = *s_sense ^ 1u;
        *s_sense = ls;
        __threadfence();
        unsigned v = atomicAdd(&g_cnt[grp], 1u);
        if (v == 7u) {
            g_cnt[grp] = 0u;
            __threadfence();
            g_sns[grp] = ls;
        } else {
            while (g_sns[grp] != ls) { }
        }
    }
    __syncthreads();
}

__global__ __launch_bounds__(512, 1) void rec_mma_kernel(
    const float* __restrict__ rfw, const float* __restrict__ rbw, int layer)
{
    extern __shared__ unsigned char smx[];
    float* zsm = (float*)(smx + OFF_Z);

    const int bx  = blockIdx.x;
    const int dir = bx >> 6;
    const int ut  = bx & 7;
    const int grp = bx >> 3;
    const int bt  = (bx >> 3) & 7;
    const int b0  = bt * 16;
    const int u0  = ut * 32;

    const float* __restrict__ R  = (dir ? rbw : rfw) + layer * 262144;
    const float* __restrict__ xz = g_xz[dir];
    float* __restrict__ outp     = layer ? g_out2[dir] : g_out1[dir];

    const int tid  = threadIdx.x;
    const int lane = tid & 31;
    const int w    = tid >> 5;
    const int wi   = w & 7;
    const int kh   = w >> 3;

    __shared__ unsigned s_sense;
    if (tid == 0) s_sense = g_sns[grp];

    for (int i = tid; i < 128 * 256; i += 512) {
        int ci = i & 127;
        int k  = i >> 7;
        float rv = R[k * 1024 + (ci >> 5) * 256 + u0 + (ci & 31)];
        __nv_bfloat16 hi = __float2bfloat16(rv);
        __nv_bfloat16 lo = __float2bfloat16(rv - __bfloat162float(hi));
        *(__nv_bfloat16*)(smx + OFF_RHI + (ci * RP + k) * 2) = hi;
        *(__nv_bfloat16*)(smx + OFF_RLO + (ci * RP + k) * 2) = lo;
    }

    {
        unsigned char* img = g_himg[dir][0][bt];
        for (int i = tid; i < 128; i += 512) {
            int pl = i >> 6;
            int wd = i & 63;
            *(uint4*)(img + pl * 8192 + ut * 1024 + wd * 16) =
                make_uint4(0, 0, 0, 0);
        }
    }
    __threadfence();
    group_barrier(grp, &s_sense);

    const int n0w   = wi * 16;
    const int brow  = n0w + (lane & 7) + 8 * ((lane >> 4) & 1);
    const int boff  = brow * (RP * 2) + 8 * ((lane >> 3) & 1) * 2;
    const uint32_t kbase = kh * 256;
    const uint32_t bHi = smem_u32(smx + OFF_RHI) + boff + kbase;
    const uint32_t bLo = smem_u32(smx + OFF_RLO) + boff + kbase;

    const int aoffb = kh * 8 * 512 + lane * 16;

    const int m_r   = lane >> 2;
    const int ccol  = 2 * (lane & 3);
    const int gcol0 = (wi >> 1) * 256 + u0 + 16 * (wi & 1) + ccol;
    float* zplane   = zsm + kh * 2112;

    const int gr  = tid >> 4;
    const int gu2 = (tid & 15) * 2;
    float cst[2] = {0.0f, 0.0f};
    const int Ug     = u0 + gu2;
    const int kstepg = Ug >> 4;
    const int jg     = Ug & 15;
    const int lposg  = (jg >> 1) & 3;
    const int regg   = ((jg >> 3) << 1) + (gr >> 3);
    const int pofs   = kstepg * 512 + ((gr & 7) * 4 + lposg) * 16 + regg * 4;

    for (int s = 0; s < 256; s++) {
        const int t = dir ? (255 - s) : s;
        const unsigned char* img_r = g_himg[dir][s & 1][bt];

        // C frags: K-half 0 seeds from xz, K-half 1 from zero
        float c0[4], c1[4];
        if (kh == 0) {
            const float* xb = xz + ((size_t)(b0 + m_r) * 256 + t) * 1024 + gcol0;
            const float* xb8 = xb + (size_t)8 * 256 * 1024;
            float2 v00 = *(const float2*)xb;
            float2 v01 = *(const float2*)(xb + 8);
            float2 v10 = *(const float2*)xb8;
            float2 v11 = *(const float2*)(xb8 + 8);
            c0[0] = v00.x; c0[1] = v00.y; c0[2] = v10.x; c0[3] = v10.y;
            c1[0] = v01.x; c1[1] = v01.y; c1[2] = v11.x; c1[3] = v11.y;
        } else {
#pragma unroll
            for (int j = 0; j < 4; j++) { c0[j] = 0.0f; c1[j] = 0.0f; }
        }

        // software-pipelined MMA: A-frags via direct LDG.128 from L2
        {
            uint4 ahq = __ldcg((const uint4*)(img_r + aoffb));
            uint4 alq = __ldcg((const uint4*)(img_r + 8192 + aoffb));
#pragma unroll
            for (int ks = 0; ks < 8; ks++) {
                uint4 ahn, aln;
                if (ks < 7) {
                    ahn = __ldcg((const uint4*)(img_r + aoffb + (ks + 1) * 512));
                    aln = __ldcg((const uint4*)(img_r + 8192 + aoffb + (ks + 1) * 512));
                }
                uint32_t bh0, bh1, bh2, bh3, bl0, bl1, bl2, bl3;
                LDSM4(bh0, bh1, bh2, bh3, bHi + 32 * ks);
                LDSM4(bl0, bl1, bl2, bl3, bLo + 32 * ks);
                MMA16816(c0[0], c0[1], c0[2], c0[3], ahq.x, ahq.y, ahq.z, ahq.w, bh0, bh1);
                MMA16816(c1[0], c1[1], c1[2], c1[3], ahq.x, ahq.y, ahq.z, ahq.w, bh2, bh3);
                MMA16816(c0[0], c0[1], c0[2], c0[3], alq.x, alq.y, alq.z, alq.w, bh0, bh1);
                MMA16816(c1[0], c1[1], c1[2], c1[3], alq.x, alq.y, alq.z, alq.w, bh2, bh3);
                MMA16816(c0[0], c0[1], c0[2], c0[3], ahq.x, ahq.y, ahq.z, ahq.w, bl0, bl1);
                MMA16816(c1[0], c1[1], c1[2], c1[3], ahq.x, ahq.y, ahq.z, ahq.w, bl2, bl3);
                ahq = ahn; alq = aln;
            }
        }

        {
            int cb = n0w + ccol;
            *(float2*)&zplane[m_r * 132 + cb]       = make_float2(c0[0], c0[1]);
            *(float2*)&zplane[(m_r + 8) * 132 + cb] = make_float2(c0[2], c0[3]);
            *(float2*)&zplane[m_r * 132 + cb + 8]       = make_float2(c1[0], c1[1]);
            *(float2*)&zplane[(m_r + 8) * 132 + cb + 8] = make_float2(c1[2], c1[3]);
        }
        __syncthreads();

        if (tid < 256) {
            unsigned char* img_w = g_himg[dir][(s + 1) & 1][bt];
            float hv[2];
#pragma unroll
            for (int j = 0; j < 2; j++) {
                int uu = gu2 + j;
                float zi = zsm[gr * 132 + uu]      + zsm[2112 + gr * 132 + uu];
                float zf = zsm[gr * 132 + 32 + uu] + zsm[2112 + gr * 132 + 32 + uu];
                float zg = zsm[gr * 132 + 64 + uu] + zsm[2112 + gr * 132 + 64 + uu];
                float zo = zsm[gr * 132 + 96 + uu] + zsm[2112 + gr * 132 + 96 + uu];
                float ig = sigf(zi);
                float fg = sigf(zf);
                float gg = tanhf_fast(zg);
                float og = sigf(zo);
                float cc = fg * cst[j] + ig * gg;
                cst[j] = cc;
                hv[j] = og * tanhf_fast(cc);
            }
            *(float2*)&outp[((size_t)(b0 + gr) * 256 + t) * 256 + u0 + gu2] =
                make_float2(hv[0], hv[1]);
            __nv_bfloat16 h0 = __float2bfloat16(hv[0]);
            __nv_bfloat16 h1 = __float2bfloat16(hv[1]);
            __nv_bfloat16 l0 = __float2bfloat16(hv[0] - __bfloat162float(h0));
            __nv_bfloat16 l1 = __float2bfloat16(hv[1] - __bfloat162float(h1));
            uint32_t whi = (uint32_t)__bfloat16_as_ushort(h0)
                         | ((uint32_t)__bfloat16_as_ushort(h1) << 16);
            uint32_t wlo = (uint32_t)__bfloat16_as_ushort(l0)
                         | ((uint32_t)__bfloat16_as_ushort(l1) << 16);
            *(uint32_t*)(img_w + pofs)        = whi;
            *(uint32_t*)(img_w + 8192 + pofs) = wlo;
        }

        group_barrier(grp, &s_sense);
    }
}

// ---------------------------------------------------------------------------
// Merge: out = 0.5 * (out2f + out1f + out2b + out1b)  (residual + average)
// ---------------------------------------------------------------------------
__global__ __launch_bounds__(256) void merge_kernel(float4* __restrict__ out) {
    int i = blockIdx.x * blockDim.x + threadIdx.x;
    const float4* a = (const float4*)g_out1[0];
    const float4* b = (const float4*)g_out2[0];
    const float4* c = (const float4*)g_out1[1];
    const float4* d = (const float4*)g_out2[1];
    float4 va = a[i], vb = b[i], vc = c[i], vd = d[i];
    float4 o;
    o.x = 0.5f * (va.x + vb.x + vc.x + vd.x);
    o.y = 0.5f * (va.y + vb.y + vc.y + vd.y);
    o.z = 0.5f * (va.z + vb.z + vc.z + vd.z);
    o.w = 0.5f * (va.w + vb.w + vc.w + vd.w);
    out[i] = o;
}

// ---------------------------------------------------------------------------
extern "C" void kernel_launch(void* const* d_in, const int* in_sizes, int n_in,
                              void* d_out, int out_size) {
    (void)in_sizes; (void)n_in; (void)out_size;
    const float* x   = (const float*)d_in[0];
    const float* kfw = (const float*)d_in[1];
    const float* rfw = (const float*)d_in[2];
    const float* bfw = (const float*)d_in[3];
    const float* kbw = (const float*)d_in[4];
    const float* rbw = (const float*)d_in[5];
    const float* bbw = (const float*)d_in[6];
    float* out = (float*)d_out;

    cudaFuncSetAttribute(rec_mma_kernel,
                         cudaFuncAttributeMaxDynamicSharedMemorySize,
                         REC_SMEM_TOTAL);
    cudaFuncSetAttribute(gemm_tc_kernel,
                         cudaFuncAttributeMaxDynamicSharedMemorySize,
                         GEMM_SMEM);

    dim3 gg(8, 256, 2);
    gemm_tc_kernel<<<gg, 256, GEMM_SMEM>>>(x, kfw, kbw, bfw, bbw, 0);
    rec_mma_kernel<<<128, 512, REC_SMEM_TOTAL>>>(rfw, rbw, 0);
    gemm_tc_kernel<<<gg, 256, GEMM_SMEM>>>(x, kfw, kbw, bfw, bbw, 1);
    rec_mma_kernel<<<128, 512, REC_SMEM_TOTAL>>>(rfw, rbw, 1);
    merge_kernel<<<8192, 256>>>((float4*)out);
}

// round 16
// speedup vs baseline: 2.4582x; 1.1345x over previous
#include <cuda_runtime.h>
#include <cuda_bf16.h>
#include <stdint.h>

// ---------------------------------------------------------------------------
// BiLSTM fp32. Round 16: conversions hoisted out of the GEMM.
//  - prep kernels convert x and all W matrices to bf16 hi/lo planes once.
//  - rec(layer0) emits out1 bf16 hi/lo as a byproduct (same words it already
//    computes for the h image) -> layer-1 GEMM gets pre-converted A.
//  - GEMM fill phase is now pure uint4 copies; MMA phase unchanged.
//  - rec otherwise identical to the proven 1130us round-15 version.
// ---------------------------------------------------------------------------

// ---- scratch (device globals; allocation is forbidden) --------------------
__device__ float g_xz[2][33554432];     // [dir][(b*T+t)*1024 + col]
__device__ float g_out1[2][8388608];    // [dir][(b*T+t)*256 + u]
__device__ float g_out2[2][8388608];
__device__ __align__(16) unsigned char g_himg[2][2][8][16384];
__device__ unsigned g_cnt[16];
__device__ volatile unsigned g_sns[16];
// pre-converted operands
__device__ __align__(16) __nv_bfloat16 g_a16x[2][8388608];      // x hi/lo
__device__ __align__(16) __nv_bfloat16 g_a16o1[2][2][8388608];  // out1 [dir][plane]
__device__ __align__(16) __nv_bfloat16 g_w16[2][2][2][262144];  // W^T [dir][layer][plane][n*256+k]

__device__ __forceinline__ float sigf(float x) {
    return 1.0f / (1.0f + __expf(-x));
}
__device__ __forceinline__ float tanhf_fast(float x) {
    return 2.0f / (1.0f + __expf(-2.0f * x)) - 1.0f;
}
__device__ __forceinline__ uint32_t smem_u32(const void* p) {
    uint32_t a;
    asm("{ .reg .u64 t; cvta.to.shared.u64 t, %1; cvt.u32.u64 %0, t; }"
        : "=r"(a) : "l"(p));
    return a;
}
__device__ __forceinline__ uint32_t bf2pack(float a, float b) {
    __nv_bfloat16 lo = __float2bfloat16(a);
    __nv_bfloat16 hi = __float2bfloat16(b);
    return (uint32_t)__bfloat16_as_ushort(lo)
         | ((uint32_t)__bfloat16_as_ushort(hi) << 16);
}

#define LDSM4(r0, r1, r2, r3, addr) \
    asm volatile("ldmatrix.sync.aligned.m8n8.x4.shared.b16 {%0,%1,%2,%3}, [%4];" \
                 : "=r"(r0), "=r"(r1), "=r"(r2), "=r"(r3) : "r"(addr))

#define MMA16816(c0, c1, c2, c3, a0, a1, a2, a3, b0, b1) \
    asm volatile("mma.sync.aligned.m16n8k16.row.col.f32.bf16.bf16.f32 " \
                 "{%0,%1,%2,%3}, {%4,%5,%6,%7}, {%8,%9}, {%0,%1,%2,%3};" \
                 : "+f"(c0), "+f"(c1), "+f"(c2), "+f"(c3) \
                 : "r"(a0), "r"(a1), "r"(a2), "r"(a3), "r"(b0), "r"(b1))

// ---------------------------------------------------------------------------
// Prep: x -> bf16 hi/lo planes. 8388608 floats, thread per float4.
// ---------------------------------------------------------------------------
__global__ __launch_bounds__(256) void conv_x_kernel(const float* __restrict__ x) {
    int i = blockIdx.x * 256 + threadIdx.x;      // 2097152 float4s
    float4 v = *(const float4*)(x + (size_t)i * 4);
    __nv_bfloat16 hx = __float2bfloat16(v.x);
    __nv_bfloat16 hy = __float2bfloat16(v.y);
    __nv_bfloat16 hz = __float2bfloat16(v.z);
    __nv_bfloat16 hw = __float2bfloat16(v.w);
    uint2 hi, lo;
    hi.x = (uint32_t)__bfloat16_as_ushort(hx) | ((uint32_t)__bfloat16_as_ushort(hy) << 16);
    hi.y = (uint32_t)__bfloat16_as_ushort(hz) | ((uint32_t)__bfloat16_as_ushort(hw) << 16);
    lo.x = bf2pack(v.x - __bfloat162float(hx), v.y - __bfloat162float(hy));
    lo.y = bf2pack(v.z - __bfloat162float(hz), v.w - __bfloat162float(hw));
    *(uint2*)(&g_a16x[0][(size_t)i * 4]) = hi;
    *(uint2*)(&g_a16x[1][(size_t)i * 4]) = lo;
}

// ---------------------------------------------------------------------------
// Prep: W[k][n] -> W^T bf16 hi/lo planes [n*256+k]. 4 matrices.
// thread: (mat, n, k4) handles k = 4*k4..4*k4+3 (coalesced 8B writes).
// ---------------------------------------------------------------------------
__global__ __launch_bounds__(256) void conv_w_kernel(
    const float* __restrict__ kfw, const float* __restrict__ kbw) {
    int gid = blockIdx.x * 256 + threadIdx.x;    // 262144
    int mat = gid >> 16;                          // 0..3
    int dir = mat >> 1, layer = mat & 1;
    int rem = gid & 65535;
    int n  = rem >> 6;
    int k4 = rem & 63;
    const float* W = (dir ? kbw : kfw) + layer * 262144;
    uint32_t hiw[2], low[2];
#pragma unroll
    for (int h = 0; h < 2; h++) {
        float a = W[(size_t)(4 * k4 + 2 * h) * 1024 + n];
        float b = W[(size_t)(4 * k4 + 2 * h + 1) * 1024 + n];
        __nv_bfloat16 ha = __float2bfloat16(a);
        __nv_bfloat16 hb = __float2bfloat16(b);
        hiw[h] = (uint32_t)__bfloat16_as_ushort(ha)
               | ((uint32_t)__bfloat16_as_ushort(hb) << 16);
        low[h] = bf2pack(a - __bfloat162float(ha), b - __bfloat162float(hb));
    }
    *(uint2*)(&g_w16[dir][layer][0][n * 256 + 4 * k4]) = make_uint2(hiw[0], hiw[1]);
    *(uint2*)(&g_w16[dir][layer][1][n * 256 + 4 * k4]) = make_uint2(low[0], low[1]);
}

// ---------------------------------------------------------------------------
// Tensor-core GEMM: C[32768,1024] = A[32768,256] @ W[256,1024] + bias
// Operands pre-converted bf16 hi/lo; fill phase = pure uint4 copies.
// ---------------------------------------------------------------------------
#define GROW 144
#define GOFF_AHI 0
#define GOFF_ALO 18432
#define GOFF_BHI 36864
#define GOFF_BLO 55296
#define GEMM_SMEM 73728

__global__ __launch_bounds__(256, 2) void gemm_tc_kernel(
    const float* __restrict__ bfw, const float* __restrict__ bbw, int layer)
{
    extern __shared__ unsigned char gsm[];
    const int dir = blockIdx.z;
    const __nv_bfloat16* __restrict__ Ahi = layer ? g_a16o1[dir][0] : g_a16x[0];
    const __nv_bfloat16* __restrict__ Alo = layer ? g_a16o1[dir][1] : g_a16x[1];
    const __nv_bfloat16* __restrict__ Bhi = g_w16[dir][layer][0];
    const __nv_bfloat16* __restrict__ Blo = g_w16[dir][layer][1];
    const float* __restrict__ bias = (dir ? bbw : bfw) + layer * 1024;
    float* __restrict__ C = g_xz[dir];

    const int m0 = blockIdx.y * 128;
    const int n0 = blockIdx.x * 128;

    const int tid  = threadIdx.x;
    const int lane = tid & 31;
    const int w    = tid >> 5;
    const int wm   = w >> 1;
    const int wn   = w & 1;

    const int aoff = ((lane & 7) + 8 * ((lane >> 3) & 1)) * GROW + 16 * (lane >> 4);
    const int boff = ((lane & 7) + 8 * ((lane >> 4) & 1)) * GROW
                   + 16 * ((lane >> 3) & 1);
    const uint32_t aHiB = smem_u32(gsm + GOFF_AHI) + wm * 32 * GROW + aoff;
    const uint32_t aLoB = smem_u32(gsm + GOFF_ALO) + wm * 32 * GROW + aoff;
    const uint32_t bHiB = smem_u32(gsm + GOFF_BHI) + wn * 64 * GROW + boff;
    const uint32_t bLoB = smem_u32(gsm + GOFF_BLO) + wn * 64 * GROW + boff;

    float c[16][4];
#pragma unroll
    for (int ng = 0; ng < 4; ng++)
#pragma unroll
        for (int h = 0; h < 2; h++) {
            float2 bv = *(const float2*)&bias[n0 + wn * 64 + ng * 16 + h * 8
                                              + 2 * (lane & 3)];
#pragma unroll
            for (int mi = 0; mi < 2; mi++) {
                int f = mi * 8 + 2 * ng + h;
                c[f][0] = bv.x; c[f][1] = bv.y;
                c[f][2] = bv.x; c[f][3] = bv.y;
            }
        }

    for (int kc = 0; kc < 256; kc += 64) {
        // fill: 1024 uint4 per matrix-plane; thread does 4 per plane
#pragma unroll
        for (int j = 0; j < 4; j++) {
            int idx = tid + 256 * j;             // 0..1023
            int r  = idx >> 3;                   // row 0..127
            int c8 = idx & 7;                    // uint4 within 64-elem row
            size_t gofs = (size_t)(m0 + r) * 256 + kc + c8 * 8;
            *(uint4*)(gsm + GOFF_AHI + r * GROW + c8 * 16) =
                *(const uint4*)(Ahi + gofs);
            *(uint4*)(gsm + GOFF_ALO + r * GROW + c8 * 16) =
                *(const uint4*)(Alo + gofs);
            size_t bofs = (size_t)(n0 + r) * 256 + kc + c8 * 8;
            *(uint4*)(gsm + GOFF_BHI + r * GROW + c8 * 16) =
                *(const uint4*)(Bhi + bofs);
            *(uint4*)(gsm + GOFF_BLO + r * GROW + c8 * 16) =
                *(const uint4*)(Blo + bofs);
        }
        __syncthreads();

#pragma unroll
        for (int ks = 0; ks < 4; ks++) {
            uint32_t ah[2][4], al[2][4];
#pragma unroll
            for (int mi = 0; mi < 2; mi++) {
                LDSM4(ah[mi][0], ah[mi][1], ah[mi][2], ah[mi][3],
                      aHiB + mi * 16 * GROW + 32 * ks);
                LDSM4(al[mi][0], al[mi][1], al[mi][2], al[mi][3],
                      aLoB + mi * 16 * GROW + 32 * ks);
            }
#pragma unroll
            for (int ng = 0; ng < 4; ng++) {
                uint32_t bh[4], bl[4];
                LDSM4(bh[0], bh[1], bh[2], bh[3], bHiB + ng * 16 * GROW + 32 * ks);
                LDSM4(bl[0], bl[1], bl[2], bl[3], bLoB + ng * 16 * GROW + 32 * ks);
#pragma unroll
                for (int mi = 0; mi < 2; mi++) {
                    int f0 = mi * 8 + 2 * ng, f1 = f0 + 1;
                    MMA16816(c[f0][0], c[f0][1], c[f0][2], c[f0][3],
                             ah[mi][0], ah[mi][1], ah[mi][2], ah[mi][3], bh[0], bh[1]);
                    MMA16816(c[f1][0], c[f1][1], c[f1][2], c[f1][3],
                             ah[mi][0], ah[mi][1], ah[mi][2], ah[mi][3], bh[2], bh[3]);
                    MMA16816(c[f0][0], c[f0][1], c[f0][2], c[f0][3],
                             al[mi][0], al[mi][1], al[mi][2], al[mi][3], bh[0], bh[1]);
                    MMA16816(c[f1][0], c[f1][1], c[f1][2], c[f1][3],
                             al[mi][0], al[mi][1], al[mi][2], al[mi][3], bh[2], bh[3]);
                    MMA16816(c[f0][0], c[f0][1], c[f0][2], c[f0][3],
                             ah[mi][0], ah[mi][1], ah[mi][2], ah[mi][3], bl[0], bl[1]);
                    MMA16816(c[f1][0], c[f1][1], c[f1][2], c[f1][3],
                             ah[mi][0], ah[mi][1], ah[mi][2], ah[mi][3], bl[2], bl[3]);
                }
            }
        }
        __syncthreads();
    }

    const int r0 = m0 + wm * 32 + (lane >> 2);
    const int cb = n0 + wn * 64 + 2 * (lane & 3);
#pragma unroll
    for (int mi = 0; mi < 2; mi++)
#pragma unroll
        for (int ni = 0; ni < 8; ni++) {
            int f = mi * 8 + ni;
            int col = cb + ni * 8;
            *(float2*)&C[(size_t)(r0 + mi * 16) * 1024 + col] =
                make_float2(c[f][0], c[f][1]);
            *(float2*)&C[(size_t)(r0 + mi * 16 + 8) * 1024 + col] =
                make_float2(c[f][2], c[f][3]);
        }
}

// ---------------------------------------------------------------------------
// Tensor-core recurrence (round-15 version; layer0 also writes out1 bf16
// hi/lo planes as byproduct).
// ---------------------------------------------------------------------------
#define RP 264
#define OFF_RHI 0
#define OFF_RLO 67584
#define OFF_Z   135168
#define REC_SMEM_TOTAL (135168 + 16896)

__device__ __forceinline__ void group_barrier(int grp, unsigned* s_sense) {
    __syncthreads();
    if (threadIdx.x == 0) {
        unsigned ls = *s_sense ^ 1u;
        *s_sense = ls;
        __threadfence();
        unsigned v = atomicAdd(&g_cnt[grp], 1u);
        if (v == 7u) {
            g_cnt[grp] = 0u;
            __threadfence();
            g_sns[grp] = ls;
        } else {
            while (g_sns[grp] != ls) { }
        }
    }
    __syncthreads();
}

__global__ __launch_bounds__(512, 1) void rec_mma_kernel(
    const float* __restrict__ rfw, const float* __restrict__ rbw, int layer)
{
    extern __shared__ unsigned char smx[];
    float* zsm = (float*)(smx + OFF_Z);

    const int bx  = blockIdx.x;
    const int dir = bx >> 6;
    const int ut  = bx & 7;
    const int grp = bx >> 3;
    const int bt  = (bx >> 3) & 7;
    const int b0  = bt * 16;
    const int u0  = ut * 32;

    const float* __restrict__ R  = (dir ? rbw : rfw) + layer * 262144;
    const float* __restrict__ xz = g_xz[dir];
    float* __restrict__ outp     = layer ? g_out2[dir] : g_out1[dir];

    const int tid  = threadIdx.x;
    const int lane = tid & 31;
    const int w    = tid >> 5;
    const int wi   = w & 7;
    const int kh   = w >> 3;

    __shared__ unsigned s_sense;
    if (tid == 0) s_sense = g_sns[grp];

    for (int i = tid; i < 128 * 256; i += 512) {
        int ci = i & 127;
        int k  = i >> 7;
        float rv = R[k * 1024 + (ci >> 5) * 256 + u0 + (ci & 31)];
        __nv_bfloat16 hi = __float2bfloat16(rv);
        __nv_bfloat16 lo = __float2bfloat16(rv - __bfloat162float(hi));
        *(__nv_bfloat16*)(smx + OFF_RHI + (ci * RP + k) * 2) = hi;
        *(__nv_bfloat16*)(smx + OFF_RLO + (ci * RP + k) * 2) = lo;
    }

    {
        unsigned char* img = g_himg[dir][0][bt];
        for (int i = tid; i < 128; i += 512) {
            int pl = i >> 6;
            int wd = i & 63;
            *(uint4*)(img + pl * 8192 + ut * 1024 + wd * 16) =
                make_uint4(0, 0, 0, 0);
        }
    }
    __threadfence();
    group_barrier(grp, &s_sense);

    const int n0w   = wi * 16;
    const int brow  = n0w + (lane & 7) + 8 * ((lane >> 4) & 1);
    const int boff  = brow * (RP * 2) + 8 * ((lane >> 3) & 1) * 2;
    const uint32_t kbase = kh * 256;
    const uint32_t bHi = smem_u32(smx + OFF_RHI) + boff + kbase;
    const uint32_t bLo = smem_u32(smx + OFF_RLO) + boff + kbase;

    const int aoffb = kh * 8 * 512 + lane * 16;

    const int m_r   = lane >> 2;
    const int ccol  = 2 * (lane & 3);
    const int gcol0 = (wi >> 1) * 256 + u0 + 16 * (wi & 1) + ccol;
    float* zplane   = zsm + kh * 2112;

    const int gr  = tid >> 4;
    const int gu2 = (tid & 15) * 2;
    float cst[2] = {0.0f, 0.0f};
    const int Ug     = u0 + gu2;
    const int kstepg = Ug >> 4;
    const int jg     = Ug & 15;
    const int lposg  = (jg >> 1) & 3;
    const int regg   = ((jg >> 3) << 1) + (gr >> 3);
    const int pofs   = kstepg * 512 + ((gr & 7) * 4 + lposg) * 16 + regg * 4;

    uint32_t* o1hi = (uint32_t*)g_a16o1[dir][0];
    uint32_t* o1lo = (uint32_t*)g_a16o1[dir][1];

    for (int s = 0; s < 256; s++) {
        const int t = dir ? (255 - s) : s;
        const unsigned char* img_r = g_himg[dir][s & 1][bt];

        float c0[4], c1[4];
        if (kh == 0) {
            const float* xb = xz + ((size_t)(b0 + m_r) * 256 + t) * 1024 + gcol0;
            const float* xb8 = xb + (size_t)8 * 256 * 1024;
            float2 v00 = *(const float2*)xb;
            float2 v01 = *(const float2*)(xb + 8);
            float2 v10 = *(const float2*)xb8;
            float2 v11 = *(const float2*)(xb8 + 8);
            c0[0] = v00.x; c0[1] = v00.y; c0[2] = v10.x; c0[3] = v10.y;
            c1[0] = v01.x; c1[1] = v01.y; c1[2] = v11.x; c1[3] = v11.y;
        } else {
#pragma unroll
            for (int j = 0; j < 4; j++) { c0[j] = 0.0f; c1[j] = 0.0f; }
        }

        {
            uint4 ahq = __ldcg((const uint4*)(img_r + aoffb));
            uint4 alq = __ldcg((const uint4*)(img_r + 8192 + aoffb));
#pragma unroll
            for (int ks = 0; ks < 8; ks++) {
                uint4 ahn, aln;
                if (ks < 7) {
                    ahn = __ldcg((const uint4*)(img_r + aoffb + (ks + 1) * 512));
                    aln = __ldcg((const uint4*)(img_r + 8192 + aoffb + (ks + 1) * 512));
                }
                uint32_t bh0, bh1, bh2, bh3, bl0, bl1, bl2, bl3;
                LDSM4(bh0, bh1, bh2, bh3, bHi + 32 * ks);
                LDSM4(bl0, bl1, bl2, bl3, bLo + 32 * ks);
                MMA16816(c0[0], c0[1], c0[2], c0[3], ahq.x, ahq.y, ahq.z, ahq.w, bh0, bh1);
                MMA16816(c1[0], c1[1], c1[2], c1[3], ahq.x, ahq.y, ahq.z, ahq.w, bh2, bh3);
                MMA16816(c0[0], c0[1], c0[2], c0[3], alq.x, alq.y, alq.z, alq.w, bh0, bh1);
                MMA16816(c1[0], c1[1], c1[2], c1[3], alq.x, alq.y, alq.z, alq.w, bh2, bh3);
                MMA16816(c0[0], c0[1], c0[2], c0[3], ahq.x, ahq.y, ahq.z, ahq.w, bl0, bl1);
                MMA16816(c1[0], c1[1], c1[2], c1[3], ahq.x, ahq.y, ahq.z, ahq.w, bl2, bl3);
                ahq = ahn; alq = aln;
            }
        }

        {
            int cb = n0w + ccol;
            *(float2*)&zplane[m_r * 132 + cb]       = make_float2(c0[0], c0[1]);
            *(float2*)&zplane[(m_r + 8) * 132 + cb] = make_float2(c0[2], c0[3]);
            *(float2*)&zplane[m_r * 132 + cb + 8]       = make_float2(c1[0], c1[1]);
            *(float2*)&zplane[(m_r + 8) * 132 + cb + 8] = make_float2(c1[2], c1[3]);
        }
        __syncthreads();

        if (tid < 256) {
            unsigned char* img_w = g_himg[dir][(s + 1) & 1][bt];
            float hv[2];
#pragma unroll
            for (int j = 0; j < 2; j++) {
                int uu = gu2 + j;
                float zi = zsm[gr * 132 + uu]      + zsm[2112 + gr * 132 + uu];
                float zf = zsm[gr * 132 + 32 + uu] + zsm[2112 + gr * 132 + 32 + uu];
                float zg = zsm[gr * 132 + 64 + uu] + zsm[2112 + gr * 132 + 64 + uu];
                float zo = zsm[gr * 132 + 96 + uu] + zsm[2112 + gr * 132 + 96 + uu];
                float ig = sigf(zi);
                float fg = sigf(zf);
                float gg = tanhf_fast(zg);
                float og = sigf(zo);
                float cc = fg * cst[j] + ig * gg;
                cst[j] = cc;
                hv[j] = og * tanhf_fast(cc);
            }
            size_t oidx = ((size_t)(b0 + gr) * 256 + t) * 256 + Ug;
            *(float2*)&outp[oidx] = make_float2(hv[0], hv[1]);
            __nv_bfloat16 h0 = __float2bfloat16(hv[0]);
            __nv_bfloat16 h1 = __float2bfloat16(hv[1]);
            __nv_bfloat16 l0 = __float2bfloat16(hv[0] - __bfloat162float(h0));
            __nv_bfloat16 l1 = __float2bfloat16(hv[1] - __bfloat162float(h1));
            uint32_t whi = (uint32_t)__bfloat16_as_ushort(h0)
                         | ((uint32_t)__bfloat16_as_ushort(h1) << 16);
            uint32_t wlo = (uint32_t)__bfloat16_as_ushort(l0)
                         | ((uint32_t)__bfloat16_as_ushort(l1) << 16);
            *(uint32_t*)(img_w + pofs)        = whi;
            *(uint32_t*)(img_w + 8192 + pofs) = wlo;
            if (layer == 0) {                 // byproduct: out1 bf16 planes
                o1hi[oidx >> 1] = whi;
                o1lo[oidx >> 1] = wlo;
            }
        }

        group_barrier(grp, &s_sense);
    }
}

// ---------------------------------------------------------------------------
// Merge: out = 0.5 * (out2f + out1f + out2b + out1b)  (residual + average)
// ---------------------------------------------------------------------------
__global__ __launch_bounds__(256) void merge_kernel(float4* __restrict__ out) {
    int i = blockIdx.x * blockDim.x + threadIdx.x;
    const float4* a = (const float4*)g_out1[0];
    const float4* b = (const float4*)g_out2[0];
    const float4* c = (const float4*)g_out1[1];
    const float4* d = (const float4*)g_out2[1];
    float4 va = a[i], vb = b[i], vc = c[i], vd = d[i];
    float4 o;
    o.x = 0.5f * (va.x + vb.x + vc.x + vd.x);
    o.y = 0.5f * (va.y + vb.y + vc.y + vd.y);
    o.z = 0.5f * (va.z + vb.z + vc.z + vd.z);
    o.w = 0.5f * (va.w + vb.w + vc.w + vd.w);
    out[i] = o;
}

// ---------------------------------------------------------------------------
extern "C" void kernel_launch(void* const* d_in, const int* in_sizes, int n_in,
                              void* d_out, int out_size) {
    (void)in_sizes; (void)n_in; (void)out_size;
    const float* x   = (const float*)d_in[0];
    const float* kfw = (const float*)d_in[1];
    const float* rfw = (const float*)d_in[2];
    const float* bfw = (const float*)d_in[3];
    const float* kbw = (const float*)d_in[4];
    const float* rbw = (const float*)d_in[5];
    const float* bbw = (const float*)d_in[6];
    float* out = (float*)d_out;

    cudaFuncSetAttribute(rec_mma_kernel,
                         cudaFuncAttributeMaxDynamicSharedMemorySize,
                         REC_SMEM_TOTAL);
    cudaFuncSetAttribute(gemm_tc_kernel,
                         cudaFuncAttributeMaxDynamicSharedMemorySize,
                         GEMM_SMEM);

    conv_x_kernel<<<8192, 256>>>(x);
    conv_w_kernel<<<1024, 256>>>(kfw, kbw);
    dim3 gg(8, 256, 2);
    gemm_tc_kernel<<<gg, 256, GEMM_SMEM>>>(bfw, bbw, 0);
    rec_mma_kernel<<<128, 512, REC_SMEM_TOTAL>>>(rfw, rbw, 0);
    gemm_tc_kernel<<<gg, 256, GEMM_SMEM>>>(bfw, bbw, 1);
    rec_mma_kernel<<<128, 512, REC_SMEM_TOTAL>>>(rfw, rbw, 1);
    merge_kernel<<<8192, 256>>>((float4*)out);
}